// round 12
// baseline (speedup 1.0000x reference)
#include <cuda_runtime.h>
#include <cuda_bf16.h>
#include <cstdint>

#define N_TOK   32768
#define NBATCH  64
#define NPER    512
#define DQK     128
#define MF      256
#define DV      256
#define TS      4096   /* u16 per 64x64 tile */
#define TSB     8192   /* bytes per tile */

#define INV_D4      0.29730177875068026f
#define INV_SQRT_M  0.0625f
#define EPS_PHI     1e-4f
#define EPS_NORM    1e-8f

// ---------------- scratch (all operand arrays are pre-swizzled 64x64 u16 tiles) ----------------
__device__ uint16_t g_QpH [(size_t)N_TOK * MF], g_QpL [(size_t)N_TOK * MF];   // tiles [rt512][kt4]
__device__ uint16_t g_KpTH[(size_t)MF * N_TOK], g_KpTL[(size_t)MF * N_TOK];   // tiles [tt512][ft4]
__device__ uint16_t g_VTH [(size_t)DV * N_TOK], g_VTL [(size_t)DV * N_TOK];   // tiles [tt512][vt4]
__device__ uint16_t g_omTH[(size_t)MF * DQK],   g_omTL[(size_t)MF * DQK];     // tiles [kt2][mt4]
__device__ uint16_t g_KVTH[(size_t)NBATCH * DV * MF], g_KVTL[(size_t)NBATCH * DV * MF]; // [b][kt4][vt4]
__device__ float    g_rowmax[N_TOK];
__device__ float    g_bmax[512];
__device__ unsigned g_segmax[NBATCH];
__device__ float    g_W  [512 * MF];
__device__ float    g_SVp[(size_t)512 * DV];

// ---------------- helpers ----------------
__device__ __forceinline__ uint32_t smem_u32(const void* p) {
    uint32_t a;
    asm("{ .reg .u64 t; cvta.to.shared.u64 t, %1; cvt.u32.u64 %0, t; }" : "=r"(a) : "l"(p));
    return a;
}
__device__ __forceinline__ uint32_t swz(uint32_t off) { return off ^ ((off >> 3) & 0x70u); }
__device__ __forceinline__ void ldsm4(uint32_t* r, uint32_t a) {
    asm volatile("ldmatrix.sync.aligned.m8n8.x4.shared.b16 {%0,%1,%2,%3}, [%4];"
        : "=r"(r[0]), "=r"(r[1]), "=r"(r[2]), "=r"(r[3]) : "r"(a));
}
__device__ __forceinline__ void mma16816(float* c, const uint32_t* a, const uint32_t* b) {
    asm volatile("mma.sync.aligned.m16n8k16.row.col.f32.bf16.bf16.f32 "
        "{%0,%1,%2,%3}, {%4,%5,%6,%7}, {%8,%9}, {%0,%1,%2,%3};"
        : "+f"(c[0]), "+f"(c[1]), "+f"(c[2]), "+f"(c[3])
        : "r"(a[0]), "r"(a[1]), "r"(a[2]), "r"(a[3]), "r"(b[0]), "r"(b[1]));
}
__device__ __forceinline__ void split1(float v, uint16_t& h, uint16_t& l) {
    __nv_bfloat16 hh = __float2bfloat16(v);
    __nv_bfloat16 ll = __float2bfloat16(v - __bfloat162float(hh));
    h = __bfloat16_as_ushort(hh); l = __bfloat16_as_ushort(ll);
}
__device__ __forceinline__ void split_pair(float a, float b, uint32_t& hw, uint32_t& lw) {
    uint16_t h0, l0, h1, l1;
    split1(a, h0, l0); split1(b, h1, l1);
    hw = (uint32_t)h0 | ((uint32_t)h1 << 16);
    lw = (uint32_t)l0 | ((uint32_t)l1 << 16);
}
__device__ __forceinline__ float from2(uint16_t h, uint16_t l) {
    return __bfloat162float(__ushort_as_bfloat16(h)) + __bfloat162float(__ushort_as_bfloat16(l));
}
__device__ __forceinline__ unsigned f2o(float f) {
    unsigned u = __float_as_uint(f);
    return (u & 0x80000000u) ? ~u : (u | 0x80000000u);
}
__device__ __forceinline__ float o2f(unsigned u) {
    return (u & 0x80000000u) ? __uint_as_float(u & 0x7fffffffu) : __uint_as_float(~u);
}
__device__ __forceinline__ float warpMax(float v) {
#pragma unroll
    for (int o = 16; o > 0; o >>= 1) v = fmaxf(v, __shfl_xor_sync(0xffffffffu, v, o));
    return v;
}

#define MBAR_INIT(mb, c)   asm volatile("mbarrier.init.shared.b64 [%0], %1;" :: "r"((uint32_t)(mb)), "r"((uint32_t)(c)) : "memory")
#define MBAR_EXPECT(mb, tx) asm volatile("mbarrier.arrive.expect_tx.shared.b64 _, [%0], %1;" :: "r"((uint32_t)(mb)), "r"((uint32_t)(tx)) : "memory")
#define MBAR_ARRIVE(mb)    asm volatile("mbarrier.arrive.release.cta.shared.b64 _, [%0];" :: "r"((uint32_t)(mb)) : "memory")
#define BULK_G2S(dst, src, bytes, mb) \
    asm volatile("cp.async.bulk.shared::cta.global.mbarrier::complete_tx::bytes [%0], [%1], %2, [%3];" \
        :: "r"((uint32_t)(dst)), "l"(src), "r"((uint32_t)(bytes)), "r"((uint32_t)(mb)) : "memory")
#define MBAR_WAIT(mb, ph) do {                                                     \
    uint32_t _m = (uint32_t)(mb), _p = (uint32_t)(ph), _d;                         \
    asm volatile("{ .reg .pred p; mbarrier.try_wait.parity.acquire.cta.shared::cta.b64 p, [%1], %2;" \
                 " selp.b32 %0,1,0,p; }" : "=r"(_d) : "r"(_m), "r"(_p) : "memory");\
    if (!_d) {                                                                     \
        asm volatile("{ .reg .pred P1; W%=:"                                       \
            " mbarrier.try_wait.parity.acquire.cta.shared::cta.b64 P1, [%0], %1, 0x989680;" \
            " @P1 bra.uni D%=; bra.uni W%=; D%=: }" :: "r"(_m), "r"(_p) : "memory"); \
    } } while (0)

// ---------------- warp-tiled bf16x3 GEMM on swizzled 64x64 tiles: one 64-wide K chunk ----------------
__device__ __forceinline__ void gemm_chunk(float c[2][8][4],
    uint32_t Ahi, uint32_t Alo, uint32_t Bhi, uint32_t Blo, int lane, int m0, int n0)
{
    uint32_t at[2], arx[2];
#pragma unroll
    for (int mt = 0; mt < 2; mt++) {
        int row = m0 + mt * 16;
        int rl = (row & 63) + (lane & 15);
        at[mt]  = (uint32_t)(row >> 6) * TSB + (uint32_t)rl * 128u;
        arx[mt] = (uint32_t)(rl & 7) << 4;
    }
    const uint32_t acol = (uint32_t)((lane >> 4) * 16);
    uint32_t bt[4], brx[4];
#pragma unroll
    for (int n2 = 0; n2 < 4; n2++) {
        int row = n0 + n2 * 16;
        int rl = (row & 63) + (((lane >> 4) << 3) + (lane & 7));
        bt[n2]  = (uint32_t)(row >> 6) * TSB + (uint32_t)rl * 128u;
        brx[n2] = (uint32_t)(rl & 7) << 4;
    }
    const uint32_t bcol = (uint32_t)(((lane >> 3) & 1) * 16);
#pragma unroll
    for (int ks = 0; ks < 4; ks++) {
        uint32_t ah[2][4], al[2][4];
#pragma unroll
        for (int mt = 0; mt < 2; mt++) {
            uint32_t o = at[mt] + ((acol + ks * 32) ^ arx[mt]);
            ldsm4(ah[mt], Ahi + o);
            ldsm4(al[mt], Alo + o);
        }
#pragma unroll
        for (int n2 = 0; n2 < 4; n2++) {
            uint32_t bh[4], bl[4];
            uint32_t o = bt[n2] + ((bcol + ks * 32) ^ brx[n2]);
            ldsm4(bh, Bhi + o);
            ldsm4(bl, Blo + o);
#pragma unroll
            for (int mt = 0; mt < 2; mt++) {
                mma16816(c[mt][n2 * 2],     ah[mt], &bh[0]);
                mma16816(c[mt][n2 * 2],     al[mt], &bh[0]);
                mma16816(c[mt][n2 * 2],     ah[mt], &bl[0]);
                mma16816(c[mt][n2 * 2 + 1], ah[mt], &bh[2]);
                mma16816(c[mt][n2 * 2 + 1], al[mt], &bh[2]);
                mma16816(c[mt][n2 * 2 + 1], ah[mt], &bl[2]);
            }
        }
    }
}

// fragments -> f32 smem dbuf, row stride DS
template <int DS>
__device__ __forceinline__ void frag_to_dbuf(float* dbuf, const float c[2][8][4],
                                             int lane, int m0, int n0)
{
    int g = lane >> 2, j = lane & 3;
#pragma unroll
    for (int mt = 0; mt < 2; mt++)
#pragma unroll
        for (int nt = 0; nt < 8; nt++) {
            int r0 = m0 + mt * 16 + g, cc = n0 + nt * 8 + j * 2;
            dbuf[r0 * DS + cc]           = c[mt][nt][0];
            dbuf[r0 * DS + cc + 1]       = c[mt][nt][1];
            dbuf[(r0 + 8) * DS + cc]     = c[mt][nt][2];
            dbuf[(r0 + 8) * DS + cc + 1] = c[mt][nt][3];
        }
}

// ---------------- omega^T (4 CTAs, blockIdx = mt) + segmax init ----------------
#define OMT_SMEM (128 * 65 * 4)
__global__ __launch_bounds__(256)
void omT_kernel(const float* __restrict__ omega) {
    extern __shared__ char smem[];
    float* tile = (float*)smem;                       // [128 k][65 m]
    const int tid = threadIdx.x;
    if (blockIdx.x == 0 && tid < NBATCH) g_segmax[tid] = 0u;
    const int mt = blockIdx.x, m0 = mt * 64;
#pragma unroll
    for (int i = 0; i < 32; i++) {
        int f = i * 256 + tid, k = f >> 6, mm = f & 63;
        tile[k * 65 + mm] = omega[k * MF + m0 + mm];
    }
    __syncthreads();
#pragma unroll
    for (int i = 0; i < 8; i++) {
        int f = i * 256 + tid, mm = f >> 5, kq = (f & 31) * 4;
        uint32_t h0, l0, h1, l1;
        split_pair(tile[kq * 65 + mm],       tile[(kq + 1) * 65 + mm], h0, l0);
        split_pair(tile[(kq + 2) * 65 + mm], tile[(kq + 3) * 65 + mm], h1, l1);
        int kt = kq >> 6, kl = kq & 63;
        size_t base = ((size_t)kt * 4 + mt) * TS;
        uint32_t off = swz((uint32_t)(mm * 128 + kl * 2)) >> 1;
        *(uint2*)&g_omTH[base + off] = make_uint2(h0, h1);
        *(uint2*)&g_omTL[base + off] = make_uint2(l0, l1);
    }
}

// ---------------- vT: (s*V)^T swizzled tiles + V colsum partials ----------------
#define VT_SMEM (64 * 129 * 4 + 256)
__global__ __launch_bounds__(256)
void vT_kernel(const float* __restrict__ V) {
    extern __shared__ char smem[];
    float* tile = (float*)smem;                       // [64 n][129 v]
    float* s_sm = (float*)(smem + 64 * 129 * 4);      // [64]
    const int tid = threadIdx.x;
    const int nt = blockIdx.x, n0 = nt * 64, v0 = blockIdx.y * 128;
    if (tid < 64) s_sm[tid] = __expf(g_rowmax[n0 + tid] - o2f(g_segmax[n0 >> 9]));
#pragma unroll
    for (int i = 0; i < 32; i++) {
        int f = i * 256 + tid, n = f >> 7, v = f & 127;
        tile[n * 129 + v] = V[(size_t)(n0 + n) * DV + v0 + v];
    }
    __syncthreads();
#pragma unroll
    for (int i = 0; i < 8; i++) {
        int f = i * 256 + tid, v = f >> 4, nq = (f & 15) * 4;
        uint32_t h0, l0, h1, l1;
        split_pair(tile[nq * 129 + v] * s_sm[nq],
                   tile[(nq + 1) * 129 + v] * s_sm[nq + 1], h0, l0);
        split_pair(tile[(nq + 2) * 129 + v] * s_sm[nq + 2],
                   tile[(nq + 3) * 129 + v] * s_sm[nq + 3], h1, l1);
        int vt = (v0 >> 6) + (v >> 6), vr = v & 63;
        size_t base = ((size_t)nt * 4 + vt) * TS;
        uint32_t off = swz((uint32_t)(vr * 128 + nq * 2)) >> 1;
        *(uint2*)&g_VTH[base + off] = make_uint2(h0, h1);
        *(uint2*)&g_VTL[base + off] = make_uint2(l0, l1);
    }
    if (tid < 128) {
        float s = 0.f;
#pragma unroll 4
        for (int n = 0; n < 64; n++) s += tile[n * 129 + tid];
        g_SVp[(size_t)nt * 256 + v0 + tid] = s;
    }
}

// ---------------- phi (fused Q+K): 64-tok x 256-feat, K in 2x64 chunks, bulk-staged B ----------------
#define PHI_MBAR  1920
#define PHI_A_HI  2048
#define PHI_A_LO  (PHI_A_HI + TSB)
#define PHI_B_HI  (PHI_A_LO + TSB)
#define PHI_B_LO  (PHI_B_HI + 4 * TSB)
#define PHI_SMEM  (PHI_B_LO + 4 * TSB)   /* 83968 */

__global__ __launch_bounds__(256, 2)
void phi_kernel(const float* __restrict__ Q, const float* __restrict__ K)
{
    extern __shared__ char smem[];
    const uint32_t sb = smem_u32(smem);
    const int tid = threadIdx.x, wid = tid >> 5, lane = tid & 31;
    const bool isq = blockIdx.x < 512;
    const int tile = blockIdx.x & 511;
    const int row0 = tile * 64;
    const float* X = isq ? Q : K;
    const int m0 = (wid & 1) * 32, n0 = (wid >> 1) * 64, warpN = wid >> 1;

    float* h_sm    = (float*)smem;               // [64]
    float* rmax_sm = (float*)(smem + 256);       // [64]
    float* rmaxp   = (float*)(smem + 512);       // [64][4]
    float* wm_sm   = (float*)(smem + 1536);      // [2]
    float* bmax_s  = (float*)(smem + 1568);      // [1]
    float* w_sm    = (float*)(smem + 1600);      // [64]
    float* dbuf    = (float*)(smem + PHI_A_HI);  // [64][257]

    if (tid == 0) MBAR_INIT(sb + PHI_MBAR, 1);
    __syncthreads();

    float c[2][8][4];
#pragma unroll
    for (int mt = 0; mt < 2; mt++)
#pragma unroll
        for (int nt = 0; nt < 8; nt++)
#pragma unroll
            for (int q = 0; q < 4; q++) c[mt][nt][q] = 0.f;

    const int arow = tid >> 2, aq = tid & 3;
#pragma unroll
    for (int ck = 0; ck < 2; ck++) {
        if (tid == 0) {
            MBAR_EXPECT(sb + PHI_MBAR, 65536);
            BULK_G2S(sb + PHI_B_HI, g_omTH + (size_t)ck * 4 * TS, 32768, sb + PHI_MBAR);
            BULK_G2S(sb + PHI_B_LO, g_omTL + (size_t)ck * 4 * TS, 32768, sb + PHI_MBAR);
        }
        const float4* xr = (const float4*)(X + (size_t)(row0 + arow) * DQK + ck * 64 + aq * 16);
        float hp = 0.f;
#pragma unroll
        for (int j = 0; j < 4; j++) {
            float4 v = xr[j];
            v.x *= INV_D4; v.y *= INV_D4; v.z *= INV_D4; v.w *= INV_D4;
            hp += v.x * v.x + v.y * v.y + v.z * v.z + v.w * v.w;
            uint32_t hwA, lwA, hwB, lwB;
            split_pair(v.x, v.y, hwA, lwA);
            split_pair(v.z, v.w, hwB, lwB);
            uint32_t off = swz((uint32_t)(arow * 128 + (aq * 16 + j * 4) * 2));
            *(uint2*)(smem + PHI_A_HI + off) = make_uint2(hwA, hwB);
            *(uint2*)(smem + PHI_A_LO + off) = make_uint2(lwA, lwB);
        }
        hp += __shfl_xor_sync(0xffffffffu, hp, 1);
        hp += __shfl_xor_sync(0xffffffffu, hp, 2);
        if ((lane & 3) == 0) {
            if (ck == 0) h_sm[arow] = 0.5f * hp;
            else         h_sm[arow] += 0.5f * hp;
        }
        MBAR_WAIT(sb + PHI_MBAR, ck & 1);
        __syncthreads();
        gemm_chunk(c, sb + PHI_A_HI, sb + PHI_A_LO, sb + PHI_B_HI, sb + PHI_B_LO,
                   lane, m0, n0);
        __syncthreads();
    }

    float rmx[2][2] = {{-3.0e38f, -3.0e38f}, {-3.0e38f, -3.0e38f}};
#pragma unroll
    for (int mt = 0; mt < 2; mt++)
#pragma unroll
        for (int nt = 0; nt < 8; nt++) {
            rmx[mt][0] = fmaxf(rmx[mt][0], fmaxf(c[mt][nt][0], c[mt][nt][1]));
            rmx[mt][1] = fmaxf(rmx[mt][1], fmaxf(c[mt][nt][2], c[mt][nt][3]));
        }
#pragma unroll
    for (int mt = 0; mt < 2; mt++)
#pragma unroll
        for (int hh = 0; hh < 2; hh++) {
            float v = rmx[mt][hh];
            v = fmaxf(v, __shfl_xor_sync(0xffffffffu, v, 1));
            v = fmaxf(v, __shfl_xor_sync(0xffffffffu, v, 2));
            rmx[mt][hh] = v;
        }
    {
        int g = lane >> 2;
        if ((lane & 3) == 0) {
            rmaxp[(m0 + g) * 4 + warpN]      = rmx[0][0];
            rmaxp[(m0 + g + 8) * 4 + warpN]  = rmx[0][1];
            rmaxp[(m0 + 16 + g) * 4 + warpN] = rmx[1][0];
            rmaxp[(m0 + 24 + g) * 4 + warpN] = rmx[1][1];
        }
    }
    __syncthreads();
    if (tid < 64) {
        float rm = fmaxf(fmaxf(rmaxp[tid * 4], rmaxp[tid * 4 + 1]),
                         fmaxf(rmaxp[tid * 4 + 2], rmaxp[tid * 4 + 3]));
        rmax_sm[tid] = rm;
        if (!isq) {
            g_rowmax[row0 + tid] = rm;
            float bm = warpMax(rm);
            if (lane == 0) wm_sm[wid] = bm;
        }
    }
    __syncthreads();
    if (!isq) {
        if (tid == 0) {
            float bm = fmaxf(wm_sm[0], wm_sm[1]);
            bmax_s[0] = bm;
            g_bmax[tile] = bm;
            atomicMax(&g_segmax[tile >> 3], f2o(bm));
        }
        __syncthreads();
        if (tid < 64) w_sm[tid] = __expf(rmax_sm[tid] - bmax_s[0]);
    }

    if (isq) {
        int g = lane >> 2, j = lane & 3;
#pragma unroll
        for (int mt = 0; mt < 2; mt++) {
            int r0 = m0 + mt * 16 + g, r1 = r0 + 8;
            float hm0 = h_sm[r0] + rmax_sm[r0];
            float hm1 = h_sm[r1] + rmax_sm[r1];
#pragma unroll
            for (int nt = 0; nt < 8; nt++) {
                int col = n0 + nt * 8 + j * 2;
                float v0 = (__expf(c[mt][nt][0] - hm0) + EPS_PHI) * INV_SQRT_M;
                float v1 = (__expf(c[mt][nt][1] - hm0) + EPS_PHI) * INV_SQRT_M;
                float v2 = (__expf(c[mt][nt][2] - hm1) + EPS_PHI) * INV_SQRT_M;
                float v3 = (__expf(c[mt][nt][3] - hm1) + EPS_PHI) * INV_SQRT_M;
                int kt = col >> 6, cl = col & 63;
                size_t base = ((size_t)tile * 4 + kt) * TS;
                uint32_t hw, lw;
                split_pair(v0, v1, hw, lw);
                uint32_t o0 = swz((uint32_t)(r0 * 128 + cl * 2)) >> 1;
                *(uint32_t*)&g_QpH[base + o0] = hw;
                *(uint32_t*)&g_QpL[base + o0] = lw;
                split_pair(v2, v3, hw, lw);
                uint32_t o1 = swz((uint32_t)(r1 * 128 + cl * 2)) >> 1;
                *(uint32_t*)&g_QpH[base + o1] = hw;
                *(uint32_t*)&g_QpL[base + o1] = lw;
            }
        }
    } else {
        int g = lane >> 2;
        float e[2][8][4];
#pragma unroll
        for (int mt = 0; mt < 2; mt++) {
            int r0 = m0 + mt * 16 + g, r1 = r0 + 8;
            float hm0 = h_sm[r0] + rmax_sm[r0];
            float hm1 = h_sm[r1] + rmax_sm[r1];
#pragma unroll
            for (int nt = 0; nt < 8; nt++) {
                e[mt][nt][0] = __expf(c[mt][nt][0] - hm0);
                e[mt][nt][1] = __expf(c[mt][nt][1] - hm0);
                e[mt][nt][2] = __expf(c[mt][nt][2] - hm1);
                e[mt][nt][3] = __expf(c[mt][nt][3] - hm1);
            }
        }
        __syncthreads();
        frag_to_dbuf<257>(dbuf, e, lane, m0, n0);
        __syncthreads();
#pragma unroll 4
        for (int i = 0; i < 32; i++) {
            int f = i * 256 + tid, feat = f >> 5, tp = (f & 31) * 2;
            uint32_t hw, lw;
            split_pair(dbuf[tp * 257 + feat], dbuf[(tp + 1) * 257 + feat], hw, lw);
            int ft = feat >> 6, fl = feat & 63;
            size_t base = ((size_t)tile * 4 + ft) * TS;
            uint32_t off = swz((uint32_t)(fl * 128 + tp * 2)) >> 1;
            *(uint32_t*)&g_KpTH[base + off] = hw;
            *(uint32_t*)&g_KpTL[base + off] = lw;
        }
        float s = 0.f;
#pragma unroll 4
        for (int t = 0; t < 64; t++) s += dbuf[t * 257 + tid] * w_sm[t];
        g_W[tile * 256 + tid] = s;
    }
}

// ---------------- kv: tile 256m x 128v, 512 thr, depth-2 bulk pipeline (full/empty mbarriers) ----------------
#define KV_AH   0
#define KV_AL   32768
#define KV_BH   65536
#define KV_BL   81920
#define KV_STG  98304
#define KV_FB0  196608
#define KV_FB1  196616
#define KV_EB0  196624
#define KV_EB1  196632
#define KV_SV   196640
#define KV_SMEM 197664

__global__ __launch_bounds__(512, 1)
void kv_kernel()
{
    extern __shared__ char smem[];
    const uint32_t sb = smem_u32(smem);
    const int tid = threadIdx.x, wid = tid >> 5, lane = tid & 31;
    const int b = blockIdx.x >> 1, vh = blockIdx.x & 1;
    const int v0 = vh * 128;
    const int m0 = (wid & 7) * 32, n0 = (wid >> 3) * 64;

    if (tid == 0) {
        MBAR_INIT(sb + KV_FB0, 1);  MBAR_INIT(sb + KV_FB1, 1);
        MBAR_INIT(sb + KV_EB0, 512); MBAR_INIT(sb + KV_EB1, 512);
    }
    __syncthreads();

    // SV partials -> smem (overlaps pipeline prologue)
    float* sv = (float*)(smem + KV_SV);            // [128]
    if (tid < 128) {
        const float* P = g_SVp + (size_t)(8 * b) * 256 + v0 + tid;
        float s = 0.f;
#pragma unroll
        for (int t = 0; t < 8; t++) s += P[t * 256];
        sv[tid] = s * EPS_PHI;
    }

    float c[2][8][4];
#pragma unroll
    for (int mt = 0; mt < 2; mt++)
#pragma unroll
        for (int nt = 0; nt < 8; nt++)
#pragma unroll
            for (int q = 0; q < 4; q++) c[mt][nt][q] = 0.f;

    if (tid == 0) {
        size_t tt = (size_t)b * 8;
        MBAR_EXPECT(sb + KV_FB0, 98304);
        BULK_G2S(sb + KV_AH, g_KpTH + tt * 4 * TS, 32768, sb + KV_FB0);
        BULK_G2S(sb + KV_AL, g_KpTL + tt * 4 * TS, 32768, sb + KV_FB0);
        BULK_G2S(sb + KV_BH, g_VTH + (tt * 4 + vh * 2) * TS, 16384, sb + KV_FB0);
        BULK_G2S(sb + KV_BL, g_VTL + (tt * 4 + vh * 2) * TS, 16384, sb + KV_FB0);
    }
    for (int ch = 0; ch < 8; ch++) {
        if (ch < 7 && tid == 0) {
            int nf = ch + 1, s1 = nf & 1;
            uint32_t st = sb + s1 * KV_STG;
            uint32_t fb = sb + (s1 ? KV_FB1 : KV_FB0);
            if (nf >= 2) {
                uint32_t eb = sb + (s1 ? KV_EB1 : KV_EB0);
                MBAR_WAIT(eb, ((nf >> 1) - 1) & 1);
            }
            size_t tt = (size_t)b * 8 + nf;
            MBAR_EXPECT(fb, 98304);
            BULK_G2S(st + KV_AH, g_KpTH + tt * 4 * TS, 32768, fb);
            BULK_G2S(st + KV_AL, g_KpTL + tt * 4 * TS, 32768, fb);
            BULK_G2S(st + KV_BH, g_VTH + (tt * 4 + vh * 2) * TS, 16384, fb);
            BULK_G2S(st + KV_BL, g_VTL + (tt * 4 + vh * 2) * TS, 16384, fb);
        }
        int s = ch & 1;
        MBAR_WAIT(sb + (s ? KV_FB1 : KV_FB0), (ch >> 1) & 1);
        uint32_t s0 = sb + s * KV_STG;
        gemm_chunk(c, s0 + KV_AH, s0 + KV_AL, s0 + KV_BH, s0 + KV_BL, lane, m0, n0);
        MBAR_ARRIVE(sb + (s ? KV_EB1 : KV_EB0));
    }
    __syncthreads();   // dbuf overlaps stage regions

    // epilogue: KVT tiles [b][kt][vt] = (D[m][v] + eps*SV[v]) / sqrt(m)
    float* dbuf = (float*)smem;                    // [256][129]
    frag_to_dbuf<129>(dbuf, c, lane, m0, n0);
    __syncthreads();
#pragma unroll 4
    for (int i = 0; i < 32; i++) {
        int f = i * 512 + tid, v = f >> 7, mp = (f & 127) * 2;
        float base = sv[v];
        float v0f = (dbuf[mp * 129 + v] + base) * INV_SQRT_M;
        float v1f = (dbuf[(mp + 1) * 129 + v] + base) * INV_SQRT_M;
        uint32_t hw, lw;
        split_pair(v0f, v1f, hw, lw);
        int kt = mp >> 6, vt = (v0 >> 6) + (v >> 6);
        size_t tbase = ((size_t)b * 16 + kt * 4 + vt) * TS;
        uint32_t off = swz((uint32_t)((v & 63) * 128 + (mp & 63) * 2)) >> 1;
        *(uint32_t*)&g_KVTH[tbase + off] = hw;
        *(uint32_t*)&g_KVTL[tbase + off] = lw;
    }
}

// ---------------- out: tile 128row x 256v, 512 thr, depth-2 bulk pipeline, norm fused ----------------
#define OU_AH   0
#define OU_AL   16384
#define OU_BH   32768
#define OU_BL   65536
#define OU_STG  98304
#define OU_FB0  196608
#define OU_FB1  196616
#define OU_EB0  196624
#define OU_EB1  196632
#define OU_KSUM 196640
#define OU_WT   197664
#define OU_NRM  197696
#define OU_SMEM 198208

__global__ __launch_bounds__(512, 1)
void out_kernel(float* __restrict__ Out)
{
    extern __shared__ char smem[];
    const uint32_t sb = smem_u32(smem);
    const int tid = threadIdx.x, wid = tid >> 5, lane = tid & 31;
    const int b = blockIdx.x >> 2, rt = blockIdx.x & 3;
    const int row0 = b * NPER + rt * 128;
    const int rt0 = row0 >> 6;
    const int m0 = (wid & 3) * 32, n0 = (wid >> 2) * 64;
    float* ksum = (float*)(smem + OU_KSUM);        // [256]
    float* wtp  = (float*)(smem + OU_WT);          // [8]

    if (tid == 0) {
        MBAR_INIT(sb + OU_FB0, 1);  MBAR_INIT(sb + OU_FB1, 1);
        MBAR_INIT(sb + OU_EB0, 512); MBAR_INIT(sb + OU_EB1, 512);
    }
    __syncthreads();

    if (tid == 0) {
        MBAR_EXPECT(sb + OU_FB0, 98304);
        BULK_G2S(sb + OU_AH,       g_QpH + ((size_t)rt0 * 4 + 0) * TS, 8192, sb + OU_FB0);
        BULK_G2S(sb + OU_AH + TSB, g_QpH + ((size_t)(rt0 + 1) * 4 + 0) * TS, 8192, sb + OU_FB0);
        BULK_G2S(sb + OU_AL,       g_QpL + ((size_t)rt0 * 4 + 0) * TS, 8192, sb + OU_FB0);
        BULK_G2S(sb + OU_AL + TSB, g_QpL + ((size_t)(rt0 + 1) * 4 + 0) * TS, 8192, sb + OU_FB0);
        BULK_G2S(sb + OU_BH, g_KVTH + ((size_t)b * 16 + 0) * TS, 32768, sb + OU_FB0);
        BULK_G2S(sb + OU_BL, g_KVTL + ((size_t)b * 16 + 0) * TS, 32768, sb + OU_FB0);
    }

    if (tid < 8) wtp[tid] = __expf(g_bmax[b * 8 + tid] - o2f(g_segmax[b]));
    __syncthreads();
    if (tid < 256) {
        float s = 0.f;
#pragma unroll
        for (int t = 0; t < 8; t++) s += g_W[(size_t)(8 * b + t) * 256 + tid] * wtp[t];
        ksum[tid] = (s + 512.0f * EPS_PHI) * INV_SQRT_M;
    }
    __syncthreads();

    float c[2][8][4];
#pragma unroll
    for (int mt = 0; mt < 2; mt++)
#pragma unroll
        for (int nt = 0; nt < 8; nt++)
#pragma unroll
            for (int q = 0; q < 4; q++) c[mt][nt][q] = 0.f;

    const int qrow = tid >> 2, qoff = (tid & 3) * 16;
    float qd = 0.f;

    for (int ch = 0; ch < 4; ch++) {
        if (ch < 3 && tid == 0) {
            int nf = ch + 1, s1 = nf & 1;
            uint32_t st = sb + s1 * OU_STG;
            uint32_t fb = sb + (s1 ? OU_FB1 : OU_FB0);
            if (nf >= 2) {
                uint32_t eb = sb + (s1 ? OU_EB1 : OU_EB0);
                MBAR_WAIT(eb, ((nf >> 1) - 1) & 1);
            }
            int kt = nf;
            MBAR_EXPECT(fb, 98304);
            BULK_G2S(st + OU_AH,       g_QpH + ((size_t)rt0 * 4 + kt) * TS, 8192, fb);
            BULK_G2S(st + OU_AH + TSB, g_QpH + ((size_t)(rt0 + 1) * 4 + kt) * TS, 8192, fb);
            BULK_G2S(st + OU_AL,       g_QpL + ((size_t)rt0 * 4 + kt) * TS, 8192, fb);
            BULK_G2S(st + OU_AL + TSB, g_QpL + ((size_t)(rt0 + 1) * 4 + kt) * TS, 8192, fb);
            BULK_G2S(st + OU_BH, g_KVTH + ((size_t)b * 16 + kt * 4) * TS, 32768, fb);
            BULK_G2S(st + OU_BL, g_KVTL + ((size_t)b * 16 + kt * 4) * TS, 32768, fb);
        }
        int s = ch & 1;
        MBAR_WAIT(sb + (s ? OU_FB1 : OU_FB0), (ch >> 1) & 1);
        // qdot partial from staged A (swizzled) against ksum
        {
            const char* AH = smem + s * OU_STG + OU_AH;
            const char* AL = smem + s * OU_STG + OU_AL;
            uint32_t tb = (uint32_t)(qrow >> 6) * TSB + (uint32_t)(qrow & 63) * 128u;
            uint32_t rx = (uint32_t)(qrow & 7) << 4;
            int k0 = ch * 64;
            float qp = 0.f;
#pragma unroll
            for (int jq = 0; jq < 4; jq++) {
                uint32_t o = tb + (((uint32_t)(qoff + jq * 4) * 2) ^ rx);
                uint2 h2 = *(const uint2*)(AH + o);
                uint2 l2 = *(const uint2*)(AL + o);
                const uint16_t* hp = (const uint16_t*)&h2;
                const uint16_t* lp = (const uint16_t*)&l2;
#pragma unroll
                for (int j = 0; j < 4; j++)
                    qp += from2(hp[j], lp[j]) * ksum[k0 + qoff + jq * 4 + j];
            }
            qd += qp;
        }
        uint32_t s0 = sb + s * OU_STG;
        gemm_chunk(c, s0 + OU_AH, s0 + OU_AL, s0 + OU_BH, s0 + OU_BL, lane, m0, n0);
        MBAR_ARRIVE(sb + (s ? OU_EB1 : OU_EB0));
    }
    __syncthreads();   // dbuf overlaps stage regions

    qd += __shfl_xor_sync(0xffffffffu, qd, 1);
    qd += __shfl_xor_sync(0xffffffffu, qd, 2);

    float* dbuf   = (float*)smem;                  // [128][257]
    float* nrm_sm = (float*)(smem + OU_NRM);       // [128]
    frag_to_dbuf<257>(dbuf, c, lane, m0, n0);
    if ((tid & 3) == 0) nrm_sm[qrow] = 1.0f / (qd + EPS_NORM);
    __syncthreads();
#pragma unroll
    for (int i = 0; i < 16; i++) {
        int f = i * 512 + tid, rr = f >> 6, c4 = (f & 63) * 4;
        float inv = nrm_sm[rr];
        float4 o = make_float4(dbuf[rr * 257 + c4] * inv, dbuf[rr * 257 + c4 + 1] * inv,
                               dbuf[rr * 257 + c4 + 2] * inv, dbuf[rr * 257 + c4 + 3] * inv);
        *(float4*)(Out + (size_t)(row0 + rr) * DV + c4) = o;
    }
}

// ---------------- launch ----------------
extern "C" void kernel_launch(void* const* d_in, const int* in_sizes, int n_in,
                              void* d_out, int out_size)
{
    (void)in_sizes; (void)n_in; (void)out_size;
    const float* Q     = (const float*)d_in[0];
    const float* K     = (const float*)d_in[1];
    const float* V     = (const float*)d_in[2];
    const float* omega = (const float*)d_in[3];
    float* Out = (float*)d_out;

    cudaFuncSetAttribute(omT_kernel,  cudaFuncAttributeMaxDynamicSharedMemorySize, OMT_SMEM);
    cudaFuncSetAttribute(vT_kernel,   cudaFuncAttributeMaxDynamicSharedMemorySize, VT_SMEM);
    cudaFuncSetAttribute(phi_kernel,  cudaFuncAttributeMaxDynamicSharedMemorySize, PHI_SMEM);
    cudaFuncSetAttribute(kv_kernel,   cudaFuncAttributeMaxDynamicSharedMemorySize, KV_SMEM);
    cudaFuncSetAttribute(out_kernel,  cudaFuncAttributeMaxDynamicSharedMemorySize, OU_SMEM);

    omT_kernel<<<4, 256, OMT_SMEM>>>(omega);
    phi_kernel<<<1024, 256, PHI_SMEM>>>(Q, K);
    vT_kernel<<<dim3(512, 2), 256, VT_SMEM>>>(V);
    kv_kernel<<<128, 512, KV_SMEM>>>();
    out_kernel<<<256, 512, OU_SMEM>>>(Out);
}

// round 13
// speedup vs baseline: 1.3995x; 1.3995x over previous
#include <cuda_runtime.h>
#include <cuda_bf16.h>
#include <cstdint>

#define N_TOK   32768
#define NBATCH  64
#define NPER    512
#define DQK     128
#define MF      256
#define DV      256
#define TS      4096   /* u16 per 64x64 tile */
#define TSB     8192   /* bytes per tile */

#define INV_D4      0.29730177875068026f
#define INV_SQRT_M  0.0625f
#define EPS_PHI     1e-4f
#define EPS_NORM    1e-8f

// ---------------- scratch (all operand arrays are pre-swizzled 64x64 u16 tiles) ----------------
__device__ uint16_t g_QpH [(size_t)N_TOK * MF], g_QpL [(size_t)N_TOK * MF];   // tiles [rt512][kt4]
__device__ uint16_t g_KpTH[(size_t)MF * N_TOK], g_KpTL[(size_t)MF * N_TOK];   // tiles [tt512][ft4]
__device__ uint16_t g_VTH [(size_t)DV * N_TOK], g_VTL [(size_t)DV * N_TOK];   // tiles [tt512][vt4]
__device__ uint16_t g_omTH[(size_t)MF * DQK],   g_omTL[(size_t)MF * DQK];     // tiles [kt2][mt4]
__device__ uint16_t g_KVTH[(size_t)NBATCH * DV * MF], g_KVTL[(size_t)NBATCH * DV * MF]; // [b][kt4][vt4]
__device__ float    g_rowmax[N_TOK];
__device__ float    g_bmax[512];
__device__ unsigned g_segmax[NBATCH];
__device__ float    g_W  [512 * MF];
__device__ float    g_SVp[(size_t)512 * DV];

// ---------------- helpers ----------------
__device__ __forceinline__ uint32_t smem_u32(const void* p) {
    uint32_t a;
    asm("{ .reg .u64 t; cvta.to.shared.u64 t, %1; cvt.u32.u64 %0, t; }" : "=r"(a) : "l"(p));
    return a;
}
__device__ __forceinline__ uint32_t swz(uint32_t off) { return off ^ ((off >> 3) & 0x70u); }
__device__ __forceinline__ void ldsm4(uint32_t* r, uint32_t a) {
    asm volatile("ldmatrix.sync.aligned.m8n8.x4.shared.b16 {%0,%1,%2,%3}, [%4];"
        : "=r"(r[0]), "=r"(r[1]), "=r"(r[2]), "=r"(r[3]) : "r"(a));
}
__device__ __forceinline__ void mma16816(float* c, const uint32_t* a, const uint32_t* b) {
    asm volatile("mma.sync.aligned.m16n8k16.row.col.f32.bf16.bf16.f32 "
        "{%0,%1,%2,%3}, {%4,%5,%6,%7}, {%8,%9}, {%0,%1,%2,%3};"
        : "+f"(c[0]), "+f"(c[1]), "+f"(c[2]), "+f"(c[3])
        : "r"(a[0]), "r"(a[1]), "r"(a[2]), "r"(a[3]), "r"(b[0]), "r"(b[1]));
}
__device__ __forceinline__ void split1(float v, uint16_t& h, uint16_t& l) {
    __nv_bfloat16 hh = __float2bfloat16(v);
    __nv_bfloat16 ll = __float2bfloat16(v - __bfloat162float(hh));
    h = __bfloat16_as_ushort(hh); l = __bfloat16_as_ushort(ll);
}
__device__ __forceinline__ void split_pair(float a, float b, uint32_t& hw, uint32_t& lw) {
    uint16_t h0, l0, h1, l1;
    split1(a, h0, l0); split1(b, h1, l1);
    hw = (uint32_t)h0 | ((uint32_t)h1 << 16);
    lw = (uint32_t)l0 | ((uint32_t)l1 << 16);
}
__device__ __forceinline__ float from2(uint16_t h, uint16_t l) {
    return __bfloat162float(__ushort_as_bfloat16(h)) + __bfloat162float(__ushort_as_bfloat16(l));
}
__device__ __forceinline__ unsigned f2o(float f) {
    unsigned u = __float_as_uint(f);
    return (u & 0x80000000u) ? ~u : (u | 0x80000000u);
}
__device__ __forceinline__ float o2f(unsigned u) {
    return (u & 0x80000000u) ? __uint_as_float(u & 0x7fffffffu) : __uint_as_float(~u);
}
__device__ __forceinline__ float warpMax(float v) {
#pragma unroll
    for (int o = 16; o > 0; o >>= 1) v = fmaxf(v, __shfl_xor_sync(0xffffffffu, v, o));
    return v;
}

#define MBAR_INIT(mb, c)   asm volatile("mbarrier.init.shared.b64 [%0], %1;" :: "r"((uint32_t)(mb)), "r"((uint32_t)(c)) : "memory")
#define MBAR_EXPECT(mb, tx) asm volatile("mbarrier.arrive.expect_tx.shared.b64 _, [%0], %1;" :: "r"((uint32_t)(mb)), "r"((uint32_t)(tx)) : "memory")
#define BULK_G2S(dst, src, bytes, mb) \
    asm volatile("cp.async.bulk.shared::cta.global.mbarrier::complete_tx::bytes [%0], [%1], %2, [%3];" \
        :: "r"((uint32_t)(dst)), "l"(src), "r"((uint32_t)(bytes)), "r"((uint32_t)(mb)) : "memory")
#define MBAR_WAIT(mb, ph) do {                                                     \
    uint32_t _m = (uint32_t)(mb), _p = (uint32_t)(ph), _d;                         \
    asm volatile("{ .reg .pred p; mbarrier.try_wait.parity.acquire.cta.shared::cta.b64 p, [%1], %2;" \
                 " selp.b32 %0,1,0,p; }" : "=r"(_d) : "r"(_m), "r"(_p) : "memory");\
    if (!_d) {                                                                     \
        asm volatile("{ .reg .pred P1; W%=:"                                       \
            " mbarrier.try_wait.parity.acquire.cta.shared::cta.b64 P1, [%0], %1, 0x989680;" \
            " @P1 bra.uni D%=; bra.uni W%=; D%=: }" :: "r"(_m), "r"(_p) : "memory"); \
    } } while (0)

// ---------------- warp-tiled bf16x3 GEMM on swizzled 64x64 tiles: one 64-wide K chunk ----------------
__device__ __forceinline__ void gemm_chunk(float c[2][8][4],
    uint32_t Ahi, uint32_t Alo, uint32_t Bhi, uint32_t Blo, int lane, int m0, int n0)
{
    uint32_t at[2], arx[2];
#pragma unroll
    for (int mt = 0; mt < 2; mt++) {
        int row = m0 + mt * 16;
        int rl = (row & 63) + (lane & 15);
        at[mt]  = (uint32_t)(row >> 6) * TSB + (uint32_t)rl * 128u;
        arx[mt] = (uint32_t)(rl & 7) << 4;
    }
    const uint32_t acol = (uint32_t)((lane >> 4) * 16);
    uint32_t bt[4], brx[4];
#pragma unroll
    for (int n2 = 0; n2 < 4; n2++) {
        int row = n0 + n2 * 16;
        int rl = (row & 63) + (((lane >> 4) << 3) + (lane & 7));
        bt[n2]  = (uint32_t)(row >> 6) * TSB + (uint32_t)rl * 128u;
        brx[n2] = (uint32_t)(rl & 7) << 4;
    }
    const uint32_t bcol = (uint32_t)(((lane >> 3) & 1) * 16);
#pragma unroll
    for (int ks = 0; ks < 4; ks++) {
        uint32_t ah[2][4], al[2][4];
#pragma unroll
        for (int mt = 0; mt < 2; mt++) {
            uint32_t o = at[mt] + ((acol + ks * 32) ^ arx[mt]);
            ldsm4(ah[mt], Ahi + o);
            ldsm4(al[mt], Alo + o);
        }
#pragma unroll
        for (int n2 = 0; n2 < 4; n2++) {
            uint32_t bh[4], bl[4];
            uint32_t o = bt[n2] + ((bcol + ks * 32) ^ brx[n2]);
            ldsm4(bh, Bhi + o);
            ldsm4(bl, Blo + o);
#pragma unroll
            for (int mt = 0; mt < 2; mt++) {
                mma16816(c[mt][n2 * 2],     ah[mt], &bh[0]);
                mma16816(c[mt][n2 * 2],     al[mt], &bh[0]);
                mma16816(c[mt][n2 * 2],     ah[mt], &bl[0]);
                mma16816(c[mt][n2 * 2 + 1], ah[mt], &bh[2]);
                mma16816(c[mt][n2 * 2 + 1], al[mt], &bh[2]);
                mma16816(c[mt][n2 * 2 + 1], ah[mt], &bl[2]);
            }
        }
    }
}

// fragments -> f32 smem dbuf, row stride DS
template <int DS>
__device__ __forceinline__ void frag_to_dbuf(float* dbuf, const float c[2][8][4],
                                             int lane, int m0, int n0)
{
    int g = lane >> 2, j = lane & 3;
#pragma unroll
    for (int mt = 0; mt < 2; mt++)
#pragma unroll
        for (int nt = 0; nt < 8; nt++) {
            int r0 = m0 + mt * 16 + g, cc = n0 + nt * 8 + j * 2;
            dbuf[r0 * DS + cc]           = c[mt][nt][0];
            dbuf[r0 * DS + cc + 1]       = c[mt][nt][1];
            dbuf[(r0 + 8) * DS + cc]     = c[mt][nt][2];
            dbuf[(r0 + 8) * DS + cc + 1] = c[mt][nt][3];
        }
}

// ---------------- omega^T (4 CTAs, blockIdx = mt) + segmax init ----------------
#define OMT_SMEM (128 * 65 * 4)
__global__ __launch_bounds__(256)
void omT_kernel(const float* __restrict__ omega) {
    extern __shared__ char smem[];
    float* tile = (float*)smem;                       // [128 k][65 m]
    const int tid = threadIdx.x;
    if (blockIdx.x == 0 && tid < NBATCH) g_segmax[tid] = 0u;
    const int mt = blockIdx.x, m0 = mt * 64;
#pragma unroll
    for (int i = 0; i < 32; i++) {
        int f = i * 256 + tid, k = f >> 6, mm = f & 63;
        tile[k * 65 + mm] = omega[k * MF + m0 + mm];
    }
    __syncthreads();
#pragma unroll
    for (int i = 0; i < 8; i++) {
        int f = i * 256 + tid, mm = f >> 5, kq = (f & 31) * 4;
        uint32_t h0, l0, h1, l1;
        split_pair(tile[kq * 65 + mm],       tile[(kq + 1) * 65 + mm], h0, l0);
        split_pair(tile[(kq + 2) * 65 + mm], tile[(kq + 3) * 65 + mm], h1, l1);
        int kt = kq >> 6, kl = kq & 63;
        size_t base = ((size_t)kt * 4 + mt) * TS;
        uint32_t off = swz((uint32_t)(mm * 128 + kl * 2)) >> 1;
        *(uint2*)&g_omTH[base + off] = make_uint2(h0, h1);
        *(uint2*)&g_omTL[base + off] = make_uint2(l0, l1);
    }
}

// ---------------- vT: (s*V)^T swizzled tiles + V colsum partials ----------------
#define VT_SMEM (64 * 129 * 4 + 256)
__global__ __launch_bounds__(256)
void vT_kernel(const float* __restrict__ V) {
    extern __shared__ char smem[];
    float* tile = (float*)smem;                       // [64 n][129 v]
    float* s_sm = (float*)(smem + 64 * 129 * 4);      // [64]
    const int tid = threadIdx.x;
    const int nt = blockIdx.x, n0 = nt * 64, v0 = blockIdx.y * 128;
    if (tid < 64) s_sm[tid] = __expf(g_rowmax[n0 + tid] - o2f(g_segmax[n0 >> 9]));
#pragma unroll
    for (int i = 0; i < 32; i++) {
        int f = i * 256 + tid, n = f >> 7, v = f & 127;
        tile[n * 129 + v] = V[(size_t)(n0 + n) * DV + v0 + v];
    }
    __syncthreads();
#pragma unroll
    for (int i = 0; i < 8; i++) {
        int f = i * 256 + tid, v = f >> 4, nq = (f & 15) * 4;
        uint32_t h0, l0, h1, l1;
        split_pair(tile[nq * 129 + v] * s_sm[nq],
                   tile[(nq + 1) * 129 + v] * s_sm[nq + 1], h0, l0);
        split_pair(tile[(nq + 2) * 129 + v] * s_sm[nq + 2],
                   tile[(nq + 3) * 129 + v] * s_sm[nq + 3], h1, l1);
        int vt = (v0 >> 6) + (v >> 6), vr = v & 63;
        size_t base = ((size_t)nt * 4 + vt) * TS;
        uint32_t off = swz((uint32_t)(vr * 128 + nq * 2)) >> 1;
        *(uint2*)&g_VTH[base + off] = make_uint2(h0, h1);
        *(uint2*)&g_VTL[base + off] = make_uint2(l0, l1);
    }
    if (tid < 128) {
        float s = 0.f;
#pragma unroll 4
        for (int n = 0; n < 64; n++) s += tile[n * 129 + tid];
        g_SVp[(size_t)nt * 256 + v0 + tid] = s;
    }
}

// ---------------- phi (fused Q+K): 64-tok x 256-feat, K in 2x64 chunks, bulk-staged B ----------------
#define PHI_MBAR  1920
#define PHI_A_HI  2048
#define PHI_A_LO  (PHI_A_HI + TSB)
#define PHI_B_HI  (PHI_A_LO + TSB)
#define PHI_B_LO  (PHI_B_HI + 4 * TSB)
#define PHI_SMEM  (PHI_B_LO + 4 * TSB)   /* 83968 */

__global__ __launch_bounds__(256, 2)
void phi_kernel(const float* __restrict__ Q, const float* __restrict__ K)
{
    extern __shared__ char smem[];
    const uint32_t sb = smem_u32(smem);
    const int tid = threadIdx.x, wid = tid >> 5, lane = tid & 31;
    const bool isq = blockIdx.x < 512;
    const int tile = blockIdx.x & 511;
    const int row0 = tile * 64;
    const float* X = isq ? Q : K;
    const int m0 = (wid & 1) * 32, n0 = (wid >> 1) * 64, warpN = wid >> 1;

    float* h_sm    = (float*)smem;               // [64]
    float* rmax_sm = (float*)(smem + 256);       // [64]
    float* rmaxp   = (float*)(smem + 512);       // [64][4]
    float* wm_sm   = (float*)(smem + 1536);      // [2]
    float* bmax_s  = (float*)(smem + 1568);      // [1]
    float* w_sm    = (float*)(smem + 1600);      // [64]
    float* dbuf    = (float*)(smem + PHI_A_HI);  // [64][257]

    if (tid == 0) MBAR_INIT(sb + PHI_MBAR, 1);
    __syncthreads();

    float c[2][8][4];
#pragma unroll
    for (int mt = 0; mt < 2; mt++)
#pragma unroll
        for (int nt = 0; nt < 8; nt++)
#pragma unroll
            for (int q = 0; q < 4; q++) c[mt][nt][q] = 0.f;

    const int arow = tid >> 2, aq = tid & 3;
#pragma unroll
    for (int ck = 0; ck < 2; ck++) {
        if (tid == 0) {
            MBAR_EXPECT(sb + PHI_MBAR, 65536);
            BULK_G2S(sb + PHI_B_HI, g_omTH + (size_t)ck * 4 * TS, 32768, sb + PHI_MBAR);
            BULK_G2S(sb + PHI_B_LO, g_omTL + (size_t)ck * 4 * TS, 32768, sb + PHI_MBAR);
        }
        const float4* xr = (const float4*)(X + (size_t)(row0 + arow) * DQK + ck * 64 + aq * 16);
        float hp = 0.f;
#pragma unroll
        for (int j = 0; j < 4; j++) {
            float4 v = xr[j];
            v.x *= INV_D4; v.y *= INV_D4; v.z *= INV_D4; v.w *= INV_D4;
            hp += v.x * v.x + v.y * v.y + v.z * v.z + v.w * v.w;
            uint32_t hwA, lwA, hwB, lwB;
            split_pair(v.x, v.y, hwA, lwA);
            split_pair(v.z, v.w, hwB, lwB);
            uint32_t off = swz((uint32_t)(arow * 128 + (aq * 16 + j * 4) * 2));
            *(uint2*)(smem + PHI_A_HI + off) = make_uint2(hwA, hwB);
            *(uint2*)(smem + PHI_A_LO + off) = make_uint2(lwA, lwB);
        }
        hp += __shfl_xor_sync(0xffffffffu, hp, 1);
        hp += __shfl_xor_sync(0xffffffffu, hp, 2);
        if ((lane & 3) == 0) {
            if (ck == 0) h_sm[arow] = 0.5f * hp;
            else         h_sm[arow] += 0.5f * hp;
        }
        MBAR_WAIT(sb + PHI_MBAR, ck & 1);
        __syncthreads();
        gemm_chunk(c, sb + PHI_A_HI, sb + PHI_A_LO, sb + PHI_B_HI, sb + PHI_B_LO,
                   lane, m0, n0);
        __syncthreads();
    }

    float rmx[2][2] = {{-3.0e38f, -3.0e38f}, {-3.0e38f, -3.0e38f}};
#pragma unroll
    for (int mt = 0; mt < 2; mt++)
#pragma unroll
        for (int nt = 0; nt < 8; nt++) {
            rmx[mt][0] = fmaxf(rmx[mt][0], fmaxf(c[mt][nt][0], c[mt][nt][1]));
            rmx[mt][1] = fmaxf(rmx[mt][1], fmaxf(c[mt][nt][2], c[mt][nt][3]));
        }
#pragma unroll
    for (int mt = 0; mt < 2; mt++)
#pragma unroll
        for (int hh = 0; hh < 2; hh++) {
            float v = rmx[mt][hh];
            v = fmaxf(v, __shfl_xor_sync(0xffffffffu, v, 1));
            v = fmaxf(v, __shfl_xor_sync(0xffffffffu, v, 2));
            rmx[mt][hh] = v;
        }
    {
        int g = lane >> 2;
        if ((lane & 3) == 0) {
            rmaxp[(m0 + g) * 4 + warpN]      = rmx[0][0];
            rmaxp[(m0 + g + 8) * 4 + warpN]  = rmx[0][1];
            rmaxp[(m0 + 16 + g) * 4 + warpN] = rmx[1][0];
            rmaxp[(m0 + 24 + g) * 4 + warpN] = rmx[1][1];
        }
    }
    __syncthreads();
    if (tid < 64) {
        float rm = fmaxf(fmaxf(rmaxp[tid * 4], rmaxp[tid * 4 + 1]),
                         fmaxf(rmaxp[tid * 4 + 2], rmaxp[tid * 4 + 3]));
        rmax_sm[tid] = rm;
        if (!isq) {
            g_rowmax[row0 + tid] = rm;
            float bm = warpMax(rm);
            if (lane == 0) wm_sm[wid] = bm;
        }
    }
    __syncthreads();
    if (!isq) {
        if (tid == 0) {
            float bm = fmaxf(wm_sm[0], wm_sm[1]);
            bmax_s[0] = bm;
            g_bmax[tile] = bm;
            atomicMax(&g_segmax[tile >> 3], f2o(bm));
        }
        __syncthreads();
        if (tid < 64) w_sm[tid] = __expf(rmax_sm[tid] - bmax_s[0]);
    }

    if (isq) {
        int g = lane >> 2, j = lane & 3;
#pragma unroll
        for (int mt = 0; mt < 2; mt++) {
            int r0 = m0 + mt * 16 + g, r1 = r0 + 8;
            float hm0 = h_sm[r0] + rmax_sm[r0];
            float hm1 = h_sm[r1] + rmax_sm[r1];
#pragma unroll
            for (int nt = 0; nt < 8; nt++) {
                int col = n0 + nt * 8 + j * 2;
                float v0 = (__expf(c[mt][nt][0] - hm0) + EPS_PHI) * INV_SQRT_M;
                float v1 = (__expf(c[mt][nt][1] - hm0) + EPS_PHI) * INV_SQRT_M;
                float v2 = (__expf(c[mt][nt][2] - hm1) + EPS_PHI) * INV_SQRT_M;
                float v3 = (__expf(c[mt][nt][3] - hm1) + EPS_PHI) * INV_SQRT_M;
                int kt = col >> 6, cl = col & 63;
                size_t base = ((size_t)tile * 4 + kt) * TS;
                uint32_t hw, lw;
                split_pair(v0, v1, hw, lw);
                uint32_t o0 = swz((uint32_t)(r0 * 128 + cl * 2)) >> 1;
                *(uint32_t*)&g_QpH[base + o0] = hw;
                *(uint32_t*)&g_QpL[base + o0] = lw;
                split_pair(v2, v3, hw, lw);
                uint32_t o1 = swz((uint32_t)(r1 * 128 + cl * 2)) >> 1;
                *(uint32_t*)&g_QpH[base + o1] = hw;
                *(uint32_t*)&g_QpL[base + o1] = lw;
            }
        }
    } else {
        int g = lane >> 2;
        float e[2][8][4];
#pragma unroll
        for (int mt = 0; mt < 2; mt++) {
            int r0 = m0 + mt * 16 + g, r1 = r0 + 8;
            float hm0 = h_sm[r0] + rmax_sm[r0];
            float hm1 = h_sm[r1] + rmax_sm[r1];
#pragma unroll
            for (int nt = 0; nt < 8; nt++) {
                e[mt][nt][0] = __expf(c[mt][nt][0] - hm0);
                e[mt][nt][1] = __expf(c[mt][nt][1] - hm0);
                e[mt][nt][2] = __expf(c[mt][nt][2] - hm1);
                e[mt][nt][3] = __expf(c[mt][nt][3] - hm1);
            }
        }
        __syncthreads();
        frag_to_dbuf<257>(dbuf, e, lane, m0, n0);
        __syncthreads();
#pragma unroll 4
        for (int i = 0; i < 32; i++) {
            int f = i * 256 + tid, feat = f >> 5, tp = (f & 31) * 2;
            uint32_t hw, lw;
            split_pair(dbuf[tp * 257 + feat], dbuf[(tp + 1) * 257 + feat], hw, lw);
            int ft = feat >> 6, fl = feat & 63;
            size_t base = ((size_t)tile * 4 + ft) * TS;
            uint32_t off = swz((uint32_t)(fl * 128 + tp * 2)) >> 1;
            *(uint32_t*)&g_KpTH[base + off] = hw;
            *(uint32_t*)&g_KpTL[base + off] = lw;
        }
        float s = 0.f;
#pragma unroll 4
        for (int t = 0; t < 64; t++) s += dbuf[t * 257 + tid] * w_sm[t];
        g_W[tile * 256 + tid] = s;
    }
}

// ---------------- kv: tile 128m x 128v, 256 thr, 2 CTA/SM, single-buffer bulk ----------------
#define KV_AH   0
#define KV_AL   16384
#define KV_BH   32768
#define KV_BL   49152
#define KV_SV   66048      /* dbuf [128][129] occupies 0..66048 */
#define KV_FB   66560
#define KV_SMEM 66576

__global__ __launch_bounds__(256, 2)
void kv_kernel()
{
    extern __shared__ char smem[];
    const uint32_t sb = smem_u32(smem);
    const int tid = threadIdx.x, wid = tid >> 5, lane = tid & 31;
    const int b = blockIdx.x >> 2, mt_ = (blockIdx.x >> 1) & 1, vh = blockIdx.x & 1;
    const int v0 = vh * 128;
    const int m0 = (wid & 3) * 32, n0 = (wid >> 2) * 64;

    if (tid == 0) MBAR_INIT(sb + KV_FB, 1);
    float* sv = (float*)(smem + KV_SV);            // [128]
    if (tid < 128) {
        const float* P = g_SVp + (size_t)(8 * b) * 256 + v0 + tid;
        float s = 0.f;
#pragma unroll
        for (int t = 0; t < 8; t++) s += P[t * 256];
        sv[tid] = s * EPS_PHI;
    }
    __syncthreads();

    float c[2][8][4];
#pragma unroll
    for (int mt = 0; mt < 2; mt++)
#pragma unroll
        for (int nt = 0; nt < 8; nt++)
#pragma unroll
            for (int q = 0; q < 4; q++) c[mt][nt][q] = 0.f;

    for (int ch = 0; ch < 8; ch++) {
        if (tid == 0) {
            size_t tt = (size_t)(b * 8 + ch) * 4;
            MBAR_EXPECT(sb + KV_FB, 65536);
            BULK_G2S(sb + KV_AH, g_KpTH + (tt + mt_ * 2) * TS, 16384, sb + KV_FB);
            BULK_G2S(sb + KV_AL, g_KpTL + (tt + mt_ * 2) * TS, 16384, sb + KV_FB);
            BULK_G2S(sb + KV_BH, g_VTH + (tt + vh * 2) * TS, 16384, sb + KV_FB);
            BULK_G2S(sb + KV_BL, g_VTL + (tt + vh * 2) * TS, 16384, sb + KV_FB);
        }
        MBAR_WAIT(sb + KV_FB, ch & 1);
        gemm_chunk(c, sb + KV_AH, sb + KV_AL, sb + KV_BH, sb + KV_BL, lane, m0, n0);
        __syncthreads();
    }

    // epilogue: KVT tiles [b][kt][vt] = (D[m][v] + eps*SV[v]) / sqrt(m)
    float* dbuf = (float*)smem;                    // [128][129]
    frag_to_dbuf<129>(dbuf, c, lane, m0, n0);
    __syncthreads();
#pragma unroll 4
    for (int i = 0; i < 32; i++) {
        int f = i * 256 + tid, v = f >> 6, mp = (f & 63) * 2;
        float base = sv[v];
        float v0f = (dbuf[mp * 129 + v] + base) * INV_SQRT_M;
        float v1f = (dbuf[(mp + 1) * 129 + v] + base) * INV_SQRT_M;
        uint32_t hw, lw;
        split_pair(v0f, v1f, hw, lw);
        int kt = mt_ * 2 + (mp >> 6), vt = vh * 2 + (v >> 6);
        size_t tbase = ((size_t)b * 16 + kt * 4 + vt) * TS;
        uint32_t off = swz((uint32_t)((v & 63) * 128 + (mp & 63) * 2)) >> 1;
        *(uint32_t*)&g_KVTH[tbase + off] = hw;
        *(uint32_t*)&g_KVTL[tbase + off] = lw;
    }
}

// ---------------- out: tile 128row x 128v, 256 thr, 2 CTA/SM, single-buffer bulk, norm fused ----------------
#define OU_AH   0
#define OU_AL   16384
#define OU_BH   32768
#define OU_BL   49152
#define OU_KSUM 66048      /* dbuf [128][129] occupies 0..66048 */
#define OU_WT   67072
#define OU_NRM  67104
#define OU_FB   67616
#define OU_SMEM 67632

__global__ __launch_bounds__(256, 2)
void out_kernel(float* __restrict__ Out)
{
    extern __shared__ char smem[];
    const uint32_t sb = smem_u32(smem);
    const int tid = threadIdx.x, wid = tid >> 5, lane = tid & 31;
    const int b = blockIdx.x >> 3, rt = (blockIdx.x >> 1) & 3, vh = blockIdx.x & 1;
    const int row0 = b * NPER + rt * 128;
    const int rt0 = row0 >> 6;
    const int m0 = (wid & 3) * 32, n0 = (wid >> 2) * 64;
    float* ksum = (float*)(smem + OU_KSUM);        // [256]
    float* wtp  = (float*)(smem + OU_WT);          // [8]

    if (tid == 0) MBAR_INIT(sb + OU_FB, 1);
    if (tid < 8) wtp[tid] = __expf(g_bmax[b * 8 + tid] - o2f(g_segmax[b]));
    __syncthreads();
    {
        float s = 0.f;
#pragma unroll
        for (int t = 0; t < 8; t++) s += g_W[(size_t)(8 * b + t) * 256 + tid] * wtp[t];
        ksum[tid] = (s + 512.0f * EPS_PHI) * INV_SQRT_M;
    }
    __syncthreads();

    float c[2][8][4];
#pragma unroll
    for (int mt = 0; mt < 2; mt++)
#pragma unroll
        for (int nt = 0; nt < 8; nt++)
#pragma unroll
            for (int q = 0; q < 4; q++) c[mt][nt][q] = 0.f;

    const int qrow = tid >> 1, qoff = (tid & 1) * 32;
    float qd = 0.f;

    for (int ch = 0; ch < 4; ch++) {
        if (tid == 0) {
            MBAR_EXPECT(sb + OU_FB, 65536);
            BULK_G2S(sb + OU_AH,       g_QpH + ((size_t)rt0 * 4 + ch) * TS, 8192, sb + OU_FB);
            BULK_G2S(sb + OU_AH + TSB, g_QpH + ((size_t)(rt0 + 1) * 4 + ch) * TS, 8192, sb + OU_FB);
            BULK_G2S(sb + OU_AL,       g_QpL + ((size_t)rt0 * 4 + ch) * TS, 8192, sb + OU_FB);
            BULK_G2S(sb + OU_AL + TSB, g_QpL + ((size_t)(rt0 + 1) * 4 + ch) * TS, 8192, sb + OU_FB);
            BULK_G2S(sb + OU_BH, g_KVTH + ((size_t)b * 16 + ch * 4 + vh * 2) * TS, 16384, sb + OU_FB);
            BULK_G2S(sb + OU_BL, g_KVTL + ((size_t)b * 16 + ch * 4 + vh * 2) * TS, 16384, sb + OU_FB);
        }
        MBAR_WAIT(sb + OU_FB, ch & 1);
        // qdot partial from staged A (swizzled) against ksum
        {
            const char* AH = smem + OU_AH;
            const char* AL = smem + OU_AL;
            uint32_t tb = (uint32_t)(qrow >> 6) * TSB + (uint32_t)(qrow & 63) * 128u;
            uint32_t rx = (uint32_t)(qrow & 7) << 4;
            int k0 = ch * 64;
            float qp = 0.f;
#pragma unroll
            for (int jq = 0; jq < 8; jq++) {
                uint32_t o = tb + (((uint32_t)(qoff + jq * 4) * 2) ^ rx);
                uint2 h2 = *(const uint2*)(AH + o);
                uint2 l2 = *(const uint2*)(AL + o);
                const uint16_t* hp = (const uint16_t*)&h2;
                const uint16_t* lp = (const uint16_t*)&l2;
#pragma unroll
                for (int j = 0; j < 4; j++)
                    qp += from2(hp[j], lp[j]) * ksum[k0 + qoff + jq * 4 + j];
            }
            qd += qp;
        }
        gemm_chunk(c, sb + OU_AH, sb + OU_AL, sb + OU_BH, sb + OU_BL, lane, m0, n0);
        __syncthreads();
    }

    qd += __shfl_xor_sync(0xffffffffu, qd, 1);

    float* dbuf   = (float*)smem;                  // [128][129]
    float* nrm_sm = (float*)(smem + OU_NRM);       // [128]
    frag_to_dbuf<129>(dbuf, c, lane, m0, n0);
    if ((tid & 1) == 0) nrm_sm[qrow] = 1.0f / (qd + EPS_NORM);
    __syncthreads();
#pragma unroll
    for (int i = 0; i < 16; i++) {
        int f = i * 256 + tid, rr = f >> 5, c4 = (f & 31) * 4;
        float inv = nrm_sm[rr];
        float4 o = make_float4(dbuf[rr * 129 + c4] * inv, dbuf[rr * 129 + c4 + 1] * inv,
                               dbuf[rr * 129 + c4 + 2] * inv, dbuf[rr * 129 + c4 + 3] * inv);
        *(float4*)(Out + (size_t)(row0 + rr) * DV + vh * 128 + c4) = o;
    }
}

// ---------------- launch ----------------
extern "C" void kernel_launch(void* const* d_in, const int* in_sizes, int n_in,
                              void* d_out, int out_size)
{
    (void)in_sizes; (void)n_in; (void)out_size;
    const float* Q     = (const float*)d_in[0];
    const float* K     = (const float*)d_in[1];
    const float* V     = (const float*)d_in[2];
    const float* omega = (const float*)d_in[3];
    float* Out = (float*)d_out;

    cudaFuncSetAttribute(omT_kernel,  cudaFuncAttributeMaxDynamicSharedMemorySize, OMT_SMEM);
    cudaFuncSetAttribute(vT_kernel,   cudaFuncAttributeMaxDynamicSharedMemorySize, VT_SMEM);
    cudaFuncSetAttribute(phi_kernel,  cudaFuncAttributeMaxDynamicSharedMemorySize, PHI_SMEM);
    cudaFuncSetAttribute(kv_kernel,   cudaFuncAttributeMaxDynamicSharedMemorySize, KV_SMEM);
    cudaFuncSetAttribute(out_kernel,  cudaFuncAttributeMaxDynamicSharedMemorySize, OU_SMEM);

    omT_kernel<<<4, 256, OMT_SMEM>>>(omega);
    phi_kernel<<<1024, 256, PHI_SMEM>>>(Q, K);
    vT_kernel<<<dim3(512, 2), 256, VT_SMEM>>>(V);
    kv_kernel<<<256, 256, KV_SMEM>>>();
    out_kernel<<<512, 256, OU_SMEM>>>(Out);
}

// round 14
// speedup vs baseline: 2.1684x; 1.5494x over previous
#include <cuda_runtime.h>
#include <cuda_bf16.h>
#include <cstdint>

#define N_TOK   32768
#define NBATCH  64
#define NPER    512
#define DQK     128
#define MF      256
#define DV      256
#define TS      4096   /* u16 per 64x64 tile */
#define TSB     8192   /* bytes per tile */

#define INV_D4      0.29730177875068026f
#define INV_SQRT_M  0.0625f
#define EPS_PHI     1e-4f
#define EPS_NORM    1e-8f

// ---------------- scratch: single-bf16 pre-swizzled 64x64 tiles ----------------
__device__ uint16_t g_Qp [(size_t)N_TOK * MF];      // tiles [rt512][kt4]
__device__ uint16_t g_KpT[(size_t)MF * N_TOK];      // tiles [tt512][ft4]
__device__ uint16_t g_VT [(size_t)DV * N_TOK];      // tiles [tt512][vt4]  ((s*V) hi)
__device__ uint16_t g_omT[(size_t)MF * DQK];        // tiles [kt2][mt4]
__device__ uint16_t g_KVT[(size_t)NBATCH * DV * MF];// tiles [b][kt4][vt4]
__device__ float    g_rowmax[N_TOK];
__device__ float    g_bmax[512];
__device__ unsigned g_segmax[NBATCH];
__device__ float    g_W  [512 * MF];
__device__ float    g_SVp[(size_t)512 * DV];

// ---------------- helpers ----------------
__device__ __forceinline__ uint32_t smem_u32(const void* p) {
    uint32_t a;
    asm("{ .reg .u64 t; cvta.to.shared.u64 t, %1; cvt.u32.u64 %0, t; }" : "=r"(a) : "l"(p));
    return a;
}
__device__ __forceinline__ uint32_t swz(uint32_t off) { return off ^ ((off >> 3) & 0x70u); }
__device__ __forceinline__ void ldsm4(uint32_t* r, uint32_t a) {
    asm volatile("ldmatrix.sync.aligned.m8n8.x4.shared.b16 {%0,%1,%2,%3}, [%4];"
        : "=r"(r[0]), "=r"(r[1]), "=r"(r[2]), "=r"(r[3]) : "r"(a));
}
__device__ __forceinline__ void mma16816(float* c, const uint32_t* a, const uint32_t* b) {
    asm volatile("mma.sync.aligned.m16n8k16.row.col.f32.bf16.bf16.f32 "
        "{%0,%1,%2,%3}, {%4,%5,%6,%7}, {%8,%9}, {%0,%1,%2,%3};"
        : "+f"(c[0]), "+f"(c[1]), "+f"(c[2]), "+f"(c[3])
        : "r"(a[0]), "r"(a[1]), "r"(a[2]), "r"(a[3]), "r"(b[0]), "r"(b[1]));
}
__device__ __forceinline__ uint16_t b16(float v) {
    return __bfloat16_as_ushort(__float2bfloat16(v));
}
__device__ __forceinline__ uint32_t pack2(float a, float b) {
    return (uint32_t)b16(a) | ((uint32_t)b16(b) << 16);
}
__device__ __forceinline__ void split1(float v, uint16_t& h, uint16_t& l) {
    __nv_bfloat16 hh = __float2bfloat16(v);
    __nv_bfloat16 ll = __float2bfloat16(v - __bfloat162float(hh));
    h = __bfloat16_as_ushort(hh); l = __bfloat16_as_ushort(ll);
}
__device__ __forceinline__ float bf2f(uint16_t h) {
    return __bfloat162float(__ushort_as_bfloat16(h));
}
__device__ __forceinline__ unsigned f2o(float f) {
    unsigned u = __float_as_uint(f);
    return (u & 0x80000000u) ? ~u : (u | 0x80000000u);
}
__device__ __forceinline__ float o2f(unsigned u) {
    return (u & 0x80000000u) ? __uint_as_float(u & 0x7fffffffu) : __uint_as_float(~u);
}
__device__ __forceinline__ float warpMax(float v) {
#pragma unroll
    for (int o = 16; o > 0; o >>= 1) v = fmaxf(v, __shfl_xor_sync(0xffffffffu, v, o));
    return v;
}

#define MBAR_INIT(mb, c)   asm volatile("mbarrier.init.shared.b64 [%0], %1;" :: "r"((uint32_t)(mb)), "r"((uint32_t)(c)) : "memory")
#define MBAR_EXPECT(mb, tx) asm volatile("mbarrier.arrive.expect_tx.shared.b64 _, [%0], %1;" :: "r"((uint32_t)(mb)), "r"((uint32_t)(tx)) : "memory")
#define BULK_G2S(dst, src, bytes, mb) \
    asm volatile("cp.async.bulk.shared::cta.global.mbarrier::complete_tx::bytes [%0], [%1], %2, [%3];" \
        :: "r"((uint32_t)(dst)), "l"(src), "r"((uint32_t)(bytes)), "r"((uint32_t)(mb)) : "memory")
#define MBAR_WAIT(mb, ph) do {                                                     \
    uint32_t _m = (uint32_t)(mb), _p = (uint32_t)(ph), _d;                         \
    asm volatile("{ .reg .pred p; mbarrier.try_wait.parity.acquire.cta.shared::cta.b64 p, [%1], %2;" \
                 " selp.b32 %0,1,0,p; }" : "=r"(_d) : "r"(_m), "r"(_p) : "memory");\
    if (!_d) {                                                                     \
        asm volatile("{ .reg .pred P1; W%=:"                                       \
            " mbarrier.try_wait.parity.acquire.cta.shared::cta.b64 P1, [%0], %1, 0x989680;" \
            " @P1 bra.uni D%=; bra.uni W%=; D%=: }" :: "r"(_m), "r"(_p) : "memory"); \
    } } while (0)

// ---------------- warp-tiled GEMM on swizzled 64x64 tiles: one 64-wide K chunk ----------------
// ALO=true: C += Ah*Bh + Al*Bh (A hi+lo, B hi). ALO=false: C += Ah*Bh.
template <bool ALO>
__device__ __forceinline__ void gemm_t(float c[2][8][4],
    uint32_t Ahi, uint32_t Alo, uint32_t Bhi, int lane, int m0, int n0)
{
    uint32_t at[2], arx[2];
#pragma unroll
    for (int mt = 0; mt < 2; mt++) {
        int row = m0 + mt * 16;
        int rl = (row & 63) + (lane & 15);
        at[mt]  = (uint32_t)(row >> 6) * TSB + (uint32_t)rl * 128u;
        arx[mt] = (uint32_t)(rl & 7) << 4;
    }
    const uint32_t acol = (uint32_t)((lane >> 4) * 16);
    uint32_t bt[4], brx[4];
#pragma unroll
    for (int n2 = 0; n2 < 4; n2++) {
        int row = n0 + n2 * 16;
        int rl = (row & 63) + (((lane >> 4) << 3) + (lane & 7));
        bt[n2]  = (uint32_t)(row >> 6) * TSB + (uint32_t)rl * 128u;
        brx[n2] = (uint32_t)(rl & 7) << 4;
    }
    const uint32_t bcol = (uint32_t)(((lane >> 3) & 1) * 16);
#pragma unroll
    for (int ks = 0; ks < 4; ks++) {
        uint32_t ah[2][4], al[2][4];
#pragma unroll
        for (int mt = 0; mt < 2; mt++) {
            uint32_t o = at[mt] + ((acol + ks * 32) ^ arx[mt]);
            ldsm4(ah[mt], Ahi + o);
            if (ALO) ldsm4(al[mt], Alo + o);
        }
#pragma unroll
        for (int n2 = 0; n2 < 4; n2++) {
            uint32_t bh[4];
            uint32_t o = bt[n2] + ((bcol + ks * 32) ^ brx[n2]);
            ldsm4(bh, Bhi + o);
#pragma unroll
            for (int mt = 0; mt < 2; mt++) {
                mma16816(c[mt][n2 * 2],     ah[mt], &bh[0]);
                mma16816(c[mt][n2 * 2 + 1], ah[mt], &bh[2]);
                if (ALO) {
                    mma16816(c[mt][n2 * 2],     al[mt], &bh[0]);
                    mma16816(c[mt][n2 * 2 + 1], al[mt], &bh[2]);
                }
            }
        }
    }
}

// fragments -> f32 smem dbuf, row stride DS
template <int DS>
__device__ __forceinline__ void frag_to_dbuf(float* dbuf, const float c[2][8][4],
                                             int lane, int m0, int n0)
{
    int g = lane >> 2, j = lane & 3;
#pragma unroll
    for (int mt = 0; mt < 2; mt++)
#pragma unroll
        for (int nt = 0; nt < 8; nt++) {
            int r0 = m0 + mt * 16 + g, cc = n0 + nt * 8 + j * 2;
            dbuf[r0 * DS + cc]           = c[mt][nt][0];
            dbuf[r0 * DS + cc + 1]       = c[mt][nt][1];
            dbuf[(r0 + 8) * DS + cc]     = c[mt][nt][2];
            dbuf[(r0 + 8) * DS + cc + 1] = c[mt][nt][3];
        }
}

// ---------------- omega^T (4 CTAs, blockIdx = mt) + segmax init ----------------
#define OMT_SMEM (128 * 65 * 4)
__global__ __launch_bounds__(256)
void omT_kernel(const float* __restrict__ omega) {
    extern __shared__ char smem[];
    float* tile = (float*)smem;                       // [128 k][65 m]
    const int tid = threadIdx.x;
    if (blockIdx.x == 0 && tid < NBATCH) g_segmax[tid] = 0u;
    const int mt = blockIdx.x, m0 = mt * 64;
#pragma unroll
    for (int i = 0; i < 32; i++) {
        int f = i * 256 + tid, k = f >> 6, mm = f & 63;
        tile[k * 65 + mm] = omega[k * MF + m0 + mm];
    }
    __syncthreads();
#pragma unroll
    for (int i = 0; i < 8; i++) {
        int f = i * 256 + tid, mm = f >> 5, kq = (f & 31) * 4;
        uint32_t p0 = pack2(tile[kq * 65 + mm],       tile[(kq + 1) * 65 + mm]);
        uint32_t p1 = pack2(tile[(kq + 2) * 65 + mm], tile[(kq + 3) * 65 + mm]);
        int kt = kq >> 6, kl = kq & 63;
        size_t base = ((size_t)kt * 4 + mt) * TS;
        uint32_t off = swz((uint32_t)(mm * 128 + kl * 2)) >> 1;
        *(uint2*)&g_omT[base + off] = make_uint2(p0, p1);
    }
}

// ---------------- vT: bf16(s*V) swizzled tiles + V colsum partials ----------------
#define VT_SMEM (64 * 129 * 4 + 256)
__global__ __launch_bounds__(256)
void vT_kernel(const float* __restrict__ V) {
    extern __shared__ char smem[];
    float* tile = (float*)smem;                       // [64 n][129 v]
    float* s_sm = (float*)(smem + 64 * 129 * 4);      // [64]
    const int tid = threadIdx.x;
    const int nt = blockIdx.x, n0 = nt * 64, v0 = blockIdx.y * 128;
    if (tid < 64) s_sm[tid] = __expf(g_rowmax[n0 + tid] - o2f(g_segmax[n0 >> 9]));
#pragma unroll
    for (int i = 0; i < 32; i++) {
        int f = i * 256 + tid, n = f >> 7, v = f & 127;
        tile[n * 129 + v] = V[(size_t)(n0 + n) * DV + v0 + v];
    }
    __syncthreads();
#pragma unroll
    for (int i = 0; i < 8; i++) {
        int f = i * 256 + tid, v = f >> 4, nq = (f & 15) * 4;
        uint32_t p0 = pack2(tile[nq * 129 + v] * s_sm[nq],
                            tile[(nq + 1) * 129 + v] * s_sm[nq + 1]);
        uint32_t p1 = pack2(tile[(nq + 2) * 129 + v] * s_sm[nq + 2],
                            tile[(nq + 3) * 129 + v] * s_sm[nq + 3]);
        int vt = (v0 >> 6) + (v >> 6), vr = v & 63;
        size_t base = ((size_t)nt * 4 + vt) * TS;
        uint32_t off = swz((uint32_t)(vr * 128 + nq * 2)) >> 1;
        *(uint2*)&g_VT[base + off] = make_uint2(p0, p1);
    }
    if (tid < 128) {
        float s = 0.f;
#pragma unroll 4
        for (int n = 0; n < 64; n++) s += tile[n * 129 + tid];
        g_SVp[(size_t)nt * 256 + v0 + tid] = s;
    }
}

// ---------------- phi (fused Q+K): 64-tok x 256-feat, bf16x2 (A hi+lo, omega hi) ----------------
#define PHI_MBAR  1920
#define PHI_A0H   2048
#define PHI_A0L   (PHI_A0H + TSB)
#define PHI_A1H   (PHI_A0L + TSB)
#define PHI_A1L   (PHI_A1H + TSB)
#define PHI_B0    (PHI_A1L + TSB)         /* 34816 */
#define PHI_B1    (PHI_B0 + 4 * TSB)      /* 67584 */
#define PHI_DBUF  34816                   /* overlaps B, used after gemm */
#define PHI_SMEM  (PHI_DBUF + 64 * 257 * 4 + 64)   /* 100672 */

__global__ __launch_bounds__(256, 2)
void phi_kernel(const float* __restrict__ Q, const float* __restrict__ K)
{
    extern __shared__ char smem[];
    const uint32_t sb = smem_u32(smem);
    const int tid = threadIdx.x, wid = tid >> 5, lane = tid & 31;
    const bool isq = blockIdx.x < 512;
    const int tile = blockIdx.x & 511;
    const int row0 = tile * 64;
    const float* X = isq ? Q : K;
    const int m0 = (wid & 1) * 32, n0 = (wid >> 1) * 64, warpN = wid >> 1;

    float* h_sm    = (float*)smem;               // [64]
    float* rmax_sm = (float*)(smem + 256);       // [64]
    float* rmaxp   = (float*)(smem + 512);       // [64][4]
    float* wm_sm   = (float*)(smem + 1536);      // [2]
    float* bmax_s  = (float*)(smem + 1568);      // [1]
    float* w_sm    = (float*)(smem + 1600);      // [64]
    float* dbuf    = (float*)(smem + PHI_DBUF);  // [64][257]

    if (tid == 0) {
        MBAR_INIT(sb + PHI_MBAR, 1);
        MBAR_EXPECT(sb + PHI_MBAR, 65536);
        BULK_G2S(sb + PHI_B0, g_omT, 32768, sb + PHI_MBAR);
        BULK_G2S(sb + PHI_B1, g_omT + (size_t)4 * TS, 32768, sb + PHI_MBAR);
    }

    // A: load X full K=128, scale, h, split hi/lo into 2 k-tiles
    const int arow = tid >> 2, aq = tid & 3;
    float hp = 0.f;
#pragma unroll
    for (int j = 0; j < 8; j++) {
        int k = aq * 32 + j * 4;
        float4 v = *(const float4*)(X + (size_t)(row0 + arow) * DQK + k);
        v.x *= INV_D4; v.y *= INV_D4; v.z *= INV_D4; v.w *= INV_D4;
        hp += v.x * v.x + v.y * v.y + v.z * v.z + v.w * v.w;
        uint16_t h0, l0, h1, l1, h2, l2, h3, l3;
        split1(v.x, h0, l0); split1(v.y, h1, l1);
        split1(v.z, h2, l2); split1(v.w, h3, l3);
        uint32_t hw0 = (uint32_t)h0 | ((uint32_t)h1 << 16);
        uint32_t hw1 = (uint32_t)h2 | ((uint32_t)h3 << 16);
        uint32_t lw0 = (uint32_t)l0 | ((uint32_t)l1 << 16);
        uint32_t lw1 = (uint32_t)l2 | ((uint32_t)l3 << 16);
        int kt = k >> 6, kl = k & 63;
        uint32_t off = swz((uint32_t)(arow * 128 + kl * 2));
        uint32_t ah = kt ? PHI_A1H : PHI_A0H;
        uint32_t al = kt ? PHI_A1L : PHI_A0L;
        *(uint2*)(smem + ah + off) = make_uint2(hw0, hw1);
        *(uint2*)(smem + al + off) = make_uint2(lw0, lw1);
    }
    hp += __shfl_xor_sync(0xffffffffu, hp, 1);
    hp += __shfl_xor_sync(0xffffffffu, hp, 2);
    if ((lane & 3) == 0) h_sm[arow] = 0.5f * hp;

    float c[2][8][4];
#pragma unroll
    for (int mt = 0; mt < 2; mt++)
#pragma unroll
        for (int nt = 0; nt < 8; nt++)
#pragma unroll
            for (int q = 0; q < 4; q++) c[mt][nt][q] = 0.f;

    MBAR_WAIT(sb + PHI_MBAR, 0);
    __syncthreads();
    gemm_t<true>(c, sb + PHI_A0H, sb + PHI_A0L, sb + PHI_B0, lane, m0, n0);
    gemm_t<true>(c, sb + PHI_A1H, sb + PHI_A1L, sb + PHI_B1, lane, m0, n0);
    __syncthreads();

    float rmx[2][2] = {{-3.0e38f, -3.0e38f}, {-3.0e38f, -3.0e38f}};
#pragma unroll
    for (int mt = 0; mt < 2; mt++)
#pragma unroll
        for (int nt = 0; nt < 8; nt++) {
            rmx[mt][0] = fmaxf(rmx[mt][0], fmaxf(c[mt][nt][0], c[mt][nt][1]));
            rmx[mt][1] = fmaxf(rmx[mt][1], fmaxf(c[mt][nt][2], c[mt][nt][3]));
        }
#pragma unroll
    for (int mt = 0; mt < 2; mt++)
#pragma unroll
        for (int hh = 0; hh < 2; hh++) {
            float v = rmx[mt][hh];
            v = fmaxf(v, __shfl_xor_sync(0xffffffffu, v, 1));
            v = fmaxf(v, __shfl_xor_sync(0xffffffffu, v, 2));
            rmx[mt][hh] = v;
        }
    {
        int g = lane >> 2;
        if ((lane & 3) == 0) {
            rmaxp[(m0 + g) * 4 + warpN]      = rmx[0][0];
            rmaxp[(m0 + g + 8) * 4 + warpN]  = rmx[0][1];
            rmaxp[(m0 + 16 + g) * 4 + warpN] = rmx[1][0];
            rmaxp[(m0 + 24 + g) * 4 + warpN] = rmx[1][1];
        }
    }
    __syncthreads();
    if (tid < 64) {
        float rm = fmaxf(fmaxf(rmaxp[tid * 4], rmaxp[tid * 4 + 1]),
                         fmaxf(rmaxp[tid * 4 + 2], rmaxp[tid * 4 + 3]));
        rmax_sm[tid] = rm;
        if (!isq) {
            g_rowmax[row0 + tid] = rm;
            float bm = warpMax(rm);
            if (lane == 0) wm_sm[wid] = bm;
        }
    }
    __syncthreads();
    if (!isq) {
        if (tid == 0) {
            float bm = fmaxf(wm_sm[0], wm_sm[1]);
            bmax_s[0] = bm;
            g_bmax[tile] = bm;
            atomicMax(&g_segmax[tile >> 3], f2o(bm));
        }
        __syncthreads();
        if (tid < 64) w_sm[tid] = __expf(rmax_sm[tid] - bmax_s[0]);
    }

    if (isq) {
        // Qp: exp + eps + scale -> bf16 tiles
        int g = lane >> 2, j = lane & 3;
#pragma unroll
        for (int mt = 0; mt < 2; mt++) {
            int r0 = m0 + mt * 16 + g, r1 = r0 + 8;
            float hm0 = h_sm[r0] + rmax_sm[r0];
            float hm1 = h_sm[r1] + rmax_sm[r1];
#pragma unroll
            for (int nt = 0; nt < 8; nt++) {
                int col = n0 + nt * 8 + j * 2;
                float v0 = (__expf(c[mt][nt][0] - hm0) + EPS_PHI) * INV_SQRT_M;
                float v1 = (__expf(c[mt][nt][1] - hm0) + EPS_PHI) * INV_SQRT_M;
                float v2 = (__expf(c[mt][nt][2] - hm1) + EPS_PHI) * INV_SQRT_M;
                float v3 = (__expf(c[mt][nt][3] - hm1) + EPS_PHI) * INV_SQRT_M;
                int kt = col >> 6, cl = col & 63;
                size_t base = ((size_t)tile * 4 + kt) * TS;
                uint32_t o0 = swz((uint32_t)(r0 * 128 + cl * 2)) >> 1;
                uint32_t o1 = swz((uint32_t)(r1 * 128 + cl * 2)) >> 1;
                *(uint32_t*)&g_Qp[base + o0] = pack2(v0, v1);
                *(uint32_t*)&g_Qp[base + o1] = pack2(v2, v3);
            }
        }
    } else {
        // Kp0 -> dbuf, transposed bf16 tile stores + W partial
        int g = lane >> 2;
        float e[2][8][4];
#pragma unroll
        for (int mt = 0; mt < 2; mt++) {
            int r0 = m0 + mt * 16 + g, r1 = r0 + 8;
            float hm0 = h_sm[r0] + rmax_sm[r0];
            float hm1 = h_sm[r1] + rmax_sm[r1];
#pragma unroll
            for (int nt = 0; nt < 8; nt++) {
                e[mt][nt][0] = __expf(c[mt][nt][0] - hm0);
                e[mt][nt][1] = __expf(c[mt][nt][1] - hm0);
                e[mt][nt][2] = __expf(c[mt][nt][2] - hm1);
                e[mt][nt][3] = __expf(c[mt][nt][3] - hm1);
            }
        }
        __syncthreads();
        frag_to_dbuf<257>(dbuf, e, lane, m0, n0);
        __syncthreads();
#pragma unroll 4
        for (int i = 0; i < 32; i++) {
            int f = i * 256 + tid, feat = f >> 5, tp = (f & 31) * 2;
            int ft = feat >> 6, fl = feat & 63;
            size_t base = ((size_t)tile * 4 + ft) * TS;
            uint32_t off = swz((uint32_t)(fl * 128 + tp * 2)) >> 1;
            *(uint32_t*)&g_KpT[base + off] =
                pack2(dbuf[tp * 257 + feat], dbuf[(tp + 1) * 257 + feat]);
        }
        float s = 0.f;
#pragma unroll 4
        for (int t = 0; t < 64; t++) s += dbuf[t * 257 + tid] * w_sm[t];
        g_W[tile * 256 + tid] = s;
    }
}

// ---------------- kv: tile 128m x 128v, 256 thr, 2 CTA/SM, depth-2 bulk pipeline ----------------
#define KV_ST0  2048
#define KV_ST1  (KV_ST0 + 32768)
#define KV_SV   67584
#define KV_FB0  68096
#define KV_FB1  68104
#define KV_SMEM 68160

__global__ __launch_bounds__(256, 2)
void kv_kernel()
{
    extern __shared__ char smem[];
    const uint32_t sb = smem_u32(smem);
    const int tid = threadIdx.x, wid = tid >> 5, lane = tid & 31;
    const int b = blockIdx.x >> 2, mt_ = (blockIdx.x >> 1) & 1, vh = blockIdx.x & 1;
    const int v0 = vh * 128;
    const int m0 = (wid & 3) * 32, n0 = (wid >> 2) * 64;

    if (tid == 0) { MBAR_INIT(sb + KV_FB0, 1); MBAR_INIT(sb + KV_FB1, 1); }
    float* sv = (float*)(smem + KV_SV);            // [128]
    if (tid < 128) {
        const float* P = g_SVp + (size_t)(8 * b) * 256 + v0 + tid;
        float s = 0.f;
#pragma unroll
        for (int t = 0; t < 8; t++) s += P[t * 256];
        sv[tid] = s * EPS_PHI;
    }
    __syncthreads();

    float c[2][8][4];
#pragma unroll
    for (int mt = 0; mt < 2; mt++)
#pragma unroll
        for (int nt = 0; nt < 8; nt++)
#pragma unroll
            for (int q = 0; q < 4; q++) c[mt][nt][q] = 0.f;

    if (tid == 0) {
        size_t tt = (size_t)(b * 8) * 4;
        MBAR_EXPECT(sb + KV_FB0, 32768);
        BULK_G2S(sb + KV_ST0,         g_KpT + (tt + mt_ * 2) * TS, 16384, sb + KV_FB0);
        BULK_G2S(sb + KV_ST0 + 16384, g_VT  + (tt + vh * 2) * TS, 16384, sb + KV_FB0);
    }
    for (int ch = 0; ch < 8; ch++) {
        if (ch < 7 && tid == 0) {
            int s1 = (ch + 1) & 1;
            uint32_t st = sb + (s1 ? KV_ST1 : KV_ST0);
            uint32_t fb = sb + (s1 ? KV_FB1 : KV_FB0);
            size_t tt = (size_t)(b * 8 + ch + 1) * 4;
            MBAR_EXPECT(fb, 32768);
            BULK_G2S(st,         g_KpT + (tt + mt_ * 2) * TS, 16384, fb);
            BULK_G2S(st + 16384, g_VT  + (tt + vh * 2) * TS, 16384, fb);
        }
        int s = ch & 1;
        MBAR_WAIT(sb + (s ? KV_FB1 : KV_FB0), (ch >> 1) & 1);
        uint32_t s0 = sb + (s ? KV_ST1 : KV_ST0);
        gemm_t<false>(c, s0, 0, s0 + 16384, lane, m0, n0);
        __syncthreads();
    }

    // epilogue: KVT tiles = bf16((D + eps*SV)/sqrt(m))
    float* dbuf = (float*)smem;                    // [128][129], overlaps stages
    frag_to_dbuf<129>(dbuf, c, lane, m0, n0);
    __syncthreads();
#pragma unroll
    for (int i = 0; i < 16; i++) {
        int f = i * 256 + tid, v = f >> 5, q = (f & 31) * 4;
        float base = sv[v];
        uint32_t p0 = pack2((dbuf[q * 129 + v] + base) * INV_SQRT_M,
                            (dbuf[(q + 1) * 129 + v] + base) * INV_SQRT_M);
        uint32_t p1 = pack2((dbuf[(q + 2) * 129 + v] + base) * INV_SQRT_M,
                            (dbuf[(q + 3) * 129 + v] + base) * INV_SQRT_M);
        int kt = mt_ * 2 + (q >> 6), vt = vh * 2 + (v >> 6);
        size_t tbase = ((size_t)b * 16 + kt * 4 + vt) * TS;
        uint32_t off = swz((uint32_t)((v & 63) * 128 + (q & 63) * 2)) >> 1;
        *(uint2*)&g_KVT[tbase + off] = make_uint2(p0, p1);
    }
}

// ---------------- out: tile 128row x 128v, 256 thr, 2 CTA/SM, depth-2 bulk, norm fused ----------------
#define OU_ST0  2048
#define OU_ST1  (OU_ST0 + 32768)
#define OU_KSUM 67584
#define OU_WT   68608
#define OU_NRM  68672
#define OU_FB0  69184
#define OU_FB1  69192
#define OU_SMEM 69248

__global__ __launch_bounds__(256, 2)
void out_kernel(float* __restrict__ Out)
{
    extern __shared__ char smem[];
    const uint32_t sb = smem_u32(smem);
    const int tid = threadIdx.x, wid = tid >> 5, lane = tid & 31;
    const int b = blockIdx.x >> 3, rt = (blockIdx.x >> 1) & 3, vh = blockIdx.x & 1;
    const int row0 = b * NPER + rt * 128;
    const int rt0 = row0 >> 6;
    const int m0 = (wid & 3) * 32, n0 = (wid >> 2) * 64;
    float* ksum   = (float*)(smem + OU_KSUM);      // [256]
    float* wtp    = (float*)(smem + OU_WT);        // [8]
    float* nrm_sm = (float*)(smem + OU_NRM);       // [128]

    if (tid == 0) { MBAR_INIT(sb + OU_FB0, 1); MBAR_INIT(sb + OU_FB1, 1); }
    if (tid < 8) wtp[tid] = __expf(g_bmax[b * 8 + tid] - o2f(g_segmax[b]));
    __syncthreads();
    {
        float s = 0.f;
#pragma unroll
        for (int t = 0; t < 8; t++) s += g_W[(size_t)(8 * b + t) * 256 + tid] * wtp[t];
        ksum[tid] = (s + 512.0f * EPS_PHI) * INV_SQRT_M;
    }
    __syncthreads();

    float c[2][8][4];
#pragma unroll
    for (int mt = 0; mt < 2; mt++)
#pragma unroll
        for (int nt = 0; nt < 8; nt++)
#pragma unroll
            for (int q = 0; q < 4; q++) c[mt][nt][q] = 0.f;

    const int qrow = tid >> 1, qoff = (tid & 1) * 32;
    float qd = 0.f;

    if (tid == 0) {
        MBAR_EXPECT(sb + OU_FB0, 32768);
        BULK_G2S(sb + OU_ST0,        g_Qp + ((size_t)rt0 * 4) * TS, 8192, sb + OU_FB0);
        BULK_G2S(sb + OU_ST0 + TSB,  g_Qp + ((size_t)(rt0 + 1) * 4) * TS, 8192, sb + OU_FB0);
        BULK_G2S(sb + OU_ST0 + 16384, g_KVT + ((size_t)b * 16 + vh * 2) * TS, 16384, sb + OU_FB0);
    }
    for (int ch = 0; ch < 4; ch++) {
        if (ch < 3 && tid == 0) {
            int s1 = (ch + 1) & 1;
            uint32_t st = sb + (s1 ? OU_ST1 : OU_ST0);
            uint32_t fb = sb + (s1 ? OU_FB1 : OU_FB0);
            int kt = ch + 1;
            MBAR_EXPECT(fb, 32768);
            BULK_G2S(st,        g_Qp + ((size_t)rt0 * 4 + kt) * TS, 8192, fb);
            BULK_G2S(st + TSB,  g_Qp + ((size_t)(rt0 + 1) * 4 + kt) * TS, 8192, fb);
            BULK_G2S(st + 16384, g_KVT + ((size_t)b * 16 + kt * 4 + vh * 2) * TS, 16384, fb);
        }
        int s = ch & 1;
        MBAR_WAIT(sb + (s ? OU_FB1 : OU_FB0), (ch >> 1) & 1);
        // qdot partial from staged Qp-hi against ksum
        {
            const char* AH = smem + (s ? OU_ST1 : OU_ST0);
            uint32_t tb = (uint32_t)(qrow >> 6) * TSB + (uint32_t)(qrow & 63) * 128u;
            uint32_t rx = (uint32_t)(qrow & 7) << 4;
            int k0 = ch * 64;
            float qp = 0.f;
#pragma unroll
            for (int jq = 0; jq < 8; jq++) {
                uint32_t o = tb + (((uint32_t)(qoff + jq * 4) * 2) ^ rx);
                uint2 h2 = *(const uint2*)(AH + o);
                const uint16_t* hp = (const uint16_t*)&h2;
#pragma unroll
                for (int j = 0; j < 4; j++)
                    qp += bf2f(hp[j]) * ksum[k0 + qoff + jq * 4 + j];
            }
            qd += qp;
        }
        uint32_t s0 = sb + (s ? OU_ST1 : OU_ST0);
        gemm_t<false>(c, s0, 0, s0 + 16384, lane, m0, n0);
        __syncthreads();
    }

    qd += __shfl_xor_sync(0xffffffffu, qd, 1);
    if ((tid & 1) == 0) nrm_sm[qrow] = 1.0f / (qd + EPS_NORM);
    __syncthreads();

    // direct fragment stores / norm
    {
        int g = lane >> 2, j = lane & 3;
#pragma unroll
        for (int mt = 0; mt < 2; mt++) {
            int r0 = m0 + mt * 16 + g, r1 = r0 + 8;
            float inv0 = nrm_sm[r0], inv1 = nrm_sm[r1];
#pragma unroll
            for (int nt = 0; nt < 8; nt++) {
                int cc = vh * 128 + n0 + nt * 8 + j * 2;
                float2 o0 = make_float2(c[mt][nt][0] * inv0, c[mt][nt][1] * inv0);
                float2 o1 = make_float2(c[mt][nt][2] * inv1, c[mt][nt][3] * inv1);
                *(float2*)(Out + (size_t)(row0 + r0) * DV + cc) = o0;
                *(float2*)(Out + (size_t)(row0 + r1) * DV + cc) = o1;
            }
        }
    }
}

// ---------------- launch ----------------
extern "C" void kernel_launch(void* const* d_in, const int* in_sizes, int n_in,
                              void* d_out, int out_size)
{
    (void)in_sizes; (void)n_in; (void)out_size;
    const float* Q     = (const float*)d_in[0];
    const float* K     = (const float*)d_in[1];
    const float* V     = (const float*)d_in[2];
    const float* omega = (const float*)d_in[3];
    float* Out = (float*)d_out;

    cudaFuncSetAttribute(omT_kernel,  cudaFuncAttributeMaxDynamicSharedMemorySize, OMT_SMEM);
    cudaFuncSetAttribute(vT_kernel,   cudaFuncAttributeMaxDynamicSharedMemorySize, VT_SMEM);
    cudaFuncSetAttribute(phi_kernel,  cudaFuncAttributeMaxDynamicSharedMemorySize, PHI_SMEM);
    cudaFuncSetAttribute(kv_kernel,   cudaFuncAttributeMaxDynamicSharedMemorySize, KV_SMEM);
    cudaFuncSetAttribute(out_kernel,  cudaFuncAttributeMaxDynamicSharedMemorySize, OU_SMEM);

    omT_kernel<<<4, 256, OMT_SMEM>>>(omega);
    phi_kernel<<<1024, 256, PHI_SMEM>>>(Q, K);
    vT_kernel<<<dim3(512, 2), 256, VT_SMEM>>>(V);
    kv_kernel<<<256, 256, KV_SMEM>>>();
    out_kernel<<<512, 256, OU_SMEM>>>(Out);
}

// round 15
// speedup vs baseline: 2.2233x; 1.0253x over previous
#include <cuda_runtime.h>
#include <cuda_fp16.h>
#include <cstdint>

#define N_TOK   32768
#define NBATCH  64
#define NPER    512
#define DQK     128
#define MF      256
#define DV      256
#define TS      4096   /* u16 per 64x64 tile */
#define TSB     8192   /* bytes per tile */

#define INV_D4      0.29730177875068026f
#define EPS_PHI     1e-4f
#define EPS_NORM_S  2.56e-6f   /* 1e-8 * 256 (1/sqrt(m) cancellation) */
#define LOG2E       1.4426950408889634f

// ---------------- scratch: f16 pre-swizzled 64x64 tiles ----------------
__device__ uint16_t g_Qp [(size_t)N_TOK * MF];      // tiles [rt512][kt4]  (e+eps)
__device__ uint16_t g_KpT[(size_t)MF * N_TOK];      // tiles [tt512][ft4]  (e)
__device__ uint16_t g_VT [(size_t)DV * N_TOK];      // tiles [tt512][vt4]  (s*V)
__device__ uint16_t g_omT[(size_t)MF * DQK];        // tiles [kt2][mt4]
__device__ uint16_t g_KVT[(size_t)NBATCH * DV * MF];// tiles [b][kt4][vt4]
__device__ float    g_rowmax[N_TOK];
__device__ float    g_bmax[512];
__device__ unsigned g_segmax[NBATCH];
__device__ float    g_W  [512 * MF];
__device__ float    g_SVp[(size_t)512 * DV];

// ---------------- helpers ----------------
__device__ __forceinline__ uint32_t smem_u32(const void* p) {
    uint32_t a;
    asm("{ .reg .u64 t; cvta.to.shared.u64 t, %1; cvt.u32.u64 %0, t; }" : "=r"(a) : "l"(p));
    return a;
}
__device__ __forceinline__ uint32_t swz(uint32_t off) { return off ^ ((off >> 3) & 0x70u); }
__device__ __forceinline__ void ldsm4(uint32_t* r, uint32_t a) {
    asm volatile("ldmatrix.sync.aligned.m8n8.x4.shared.b16 {%0,%1,%2,%3}, [%4];"
        : "=r"(r[0]), "=r"(r[1]), "=r"(r[2]), "=r"(r[3]) : "r"(a));
}
__device__ __forceinline__ void mma16816(float* c, const uint32_t* a, const uint32_t* b) {
    asm volatile("mma.sync.aligned.m16n8k16.row.col.f32.f16.f16.f32 "
        "{%0,%1,%2,%3}, {%4,%5,%6,%7}, {%8,%9}, {%0,%1,%2,%3};"
        : "+f"(c[0]), "+f"(c[1]), "+f"(c[2]), "+f"(c[3])
        : "r"(a[0]), "r"(a[1]), "r"(a[2]), "r"(a[3]), "r"(b[0]), "r"(b[1]));
}
__device__ __forceinline__ uint32_t pack2h(float lo, float hi) {
    uint32_t r;
    asm("cvt.rn.f16x2.f32 %0, %1, %2;" : "=r"(r) : "f"(hi), "f"(lo));
    return r;
}
// packed exp2 of two f32 args -> f16x2 {lo=2^y0, hi=2^y1}
__device__ __forceinline__ uint32_t exp2_h2(float y0, float y1) {
    uint32_t r;
    asm("{ .reg .b32 t; cvt.rn.f16x2.f32 t, %2, %1; ex2.approx.f16x2 %0, t; }"
        : "=r"(r) : "f"(y0), "f"(y1));
    return r;
}
__device__ __forceinline__ uint32_t prmt(uint32_t a, uint32_t b, uint32_t s) {
    uint32_t r;
    asm("prmt.b32 %0, %1, %2, %3;" : "=r"(r) : "r"(a), "r"(b), "r"(s));
    return r;
}
__device__ __forceinline__ void split1h(float v, uint16_t& h, uint16_t& l) {
    __half hh = __float2half_rn(v);
    h = __half_as_ushort(hh);
    l = __half_as_ushort(__float2half_rn(v - __half2float(hh)));
}
__device__ __forceinline__ float h2f(uint16_t h) {
    return __half2float(__ushort_as_half(h));
}
__device__ __forceinline__ unsigned f2o(float f) {
    unsigned u = __float_as_uint(f);
    return (u & 0x80000000u) ? ~u : (u | 0x80000000u);
}
__device__ __forceinline__ float o2f(unsigned u) {
    return (u & 0x80000000u) ? __uint_as_float(u & 0x7fffffffu) : __uint_as_float(~u);
}
__device__ __forceinline__ float warpMax(float v) {
#pragma unroll
    for (int o = 16; o > 0; o >>= 1) v = fmaxf(v, __shfl_xor_sync(0xffffffffu, v, o));
    return v;
}

#define MBAR_INIT(mb, c)   asm volatile("mbarrier.init.shared.b64 [%0], %1;" :: "r"((uint32_t)(mb)), "r"((uint32_t)(c)) : "memory")
#define MBAR_EXPECT(mb, tx) asm volatile("mbarrier.arrive.expect_tx.shared.b64 _, [%0], %1;" :: "r"((uint32_t)(mb)), "r"((uint32_t)(tx)) : "memory")
#define BULK_G2S(dst, src, bytes, mb) \
    asm volatile("cp.async.bulk.shared::cta.global.mbarrier::complete_tx::bytes [%0], [%1], %2, [%3];" \
        :: "r"((uint32_t)(dst)), "l"(src), "r"((uint32_t)(bytes)), "r"((uint32_t)(mb)) : "memory")
#define MBAR_WAIT(mb, ph) do {                                                     \
    uint32_t _m = (uint32_t)(mb), _p = (uint32_t)(ph), _d;                         \
    asm volatile("{ .reg .pred p; mbarrier.try_wait.parity.acquire.cta.shared::cta.b64 p, [%1], %2;" \
                 " selp.b32 %0,1,0,p; }" : "=r"(_d) : "r"(_m), "r"(_p) : "memory");\
    if (!_d) {                                                                     \
        asm volatile("{ .reg .pred P1; W%=:"                                       \
            " mbarrier.try_wait.parity.acquire.cta.shared::cta.b64 P1, [%0], %1, 0x989680;" \
            " @P1 bra.uni D%=; bra.uni W%=; D%=: }" :: "r"(_m), "r"(_p) : "memory"); \
    } } while (0)

// ---------------- warp-tiled GEMM on swizzled 64x64 tiles: one 64-wide K chunk ----------------
template <bool ALO>
__device__ __forceinline__ void gemm_t(float c[2][8][4],
    uint32_t Ahi, uint32_t Alo, uint32_t Bhi, int lane, int m0, int n0)
{
    uint32_t at[2], arx[2];
#pragma unroll
    for (int mt = 0; mt < 2; mt++) {
        int row = m0 + mt * 16;
        int rl = (row & 63) + (lane & 15);
        at[mt]  = (uint32_t)(row >> 6) * TSB + (uint32_t)rl * 128u;
        arx[mt] = (uint32_t)(rl & 7) << 4;
    }
    const uint32_t acol = (uint32_t)((lane >> 4) * 16);
    uint32_t bt[4], brx[4];
#pragma unroll
    for (int n2 = 0; n2 < 4; n2++) {
        int row = n0 + n2 * 16;
        int rl = (row & 63) + (((lane >> 4) << 3) + (lane & 7));
        bt[n2]  = (uint32_t)(row >> 6) * TSB + (uint32_t)rl * 128u;
        brx[n2] = (uint32_t)(rl & 7) << 4;
    }
    const uint32_t bcol = (uint32_t)(((lane >> 3) & 1) * 16);
#pragma unroll
    for (int ks = 0; ks < 4; ks++) {
        uint32_t ah[2][4], al[2][4];
#pragma unroll
        for (int mt = 0; mt < 2; mt++) {
            uint32_t o = at[mt] + ((acol + ks * 32) ^ arx[mt]);
            ldsm4(ah[mt], Ahi + o);
            if (ALO) ldsm4(al[mt], Alo + o);
        }
#pragma unroll
        for (int n2 = 0; n2 < 4; n2++) {
            uint32_t bh[4];
            uint32_t o = bt[n2] + ((bcol + ks * 32) ^ brx[n2]);
            ldsm4(bh, Bhi + o);
#pragma unroll
            for (int mt = 0; mt < 2; mt++) {
                mma16816(c[mt][n2 * 2],     ah[mt], &bh[0]);
                mma16816(c[mt][n2 * 2 + 1], ah[mt], &bh[2]);
                if (ALO) {
                    mma16816(c[mt][n2 * 2],     al[mt], &bh[0]);
                    mma16816(c[mt][n2 * 2 + 1], al[mt], &bh[2]);
                }
            }
        }
    }
}

// fragments -> f32 smem dbuf, row stride DS
template <int DS>
__device__ __forceinline__ void frag_to_dbuf(float* dbuf, const float c[2][8][4],
                                             int lane, int m0, int n0)
{
    int g = lane >> 2, j = lane & 3;
#pragma unroll
    for (int mt = 0; mt < 2; mt++)
#pragma unroll
        for (int nt = 0; nt < 8; nt++) {
            int r0 = m0 + mt * 16 + g, cc = n0 + nt * 8 + j * 2;
            dbuf[r0 * DS + cc]           = c[mt][nt][0];
            dbuf[r0 * DS + cc + 1]       = c[mt][nt][1];
            dbuf[(r0 + 8) * DS + cc]     = c[mt][nt][2];
            dbuf[(r0 + 8) * DS + cc + 1] = c[mt][nt][3];
        }
}

// ---------------- omega^T (4 CTAs, blockIdx = mt) + segmax init ----------------
#define OMT_SMEM (128 * 65 * 4)
__global__ __launch_bounds__(256)
void omT_kernel(const float* __restrict__ omega) {
    extern __shared__ char smem[];
    float* tile = (float*)smem;                       // [128 k][65 m]
    const int tid = threadIdx.x;
    if (blockIdx.x == 0 && tid < NBATCH) g_segmax[tid] = 0u;
    const int mt = blockIdx.x, m0 = mt * 64;
#pragma unroll
    for (int i = 0; i < 32; i++) {
        int f = i * 256 + tid, k = f >> 6, mm = f & 63;
        tile[k * 65 + mm] = omega[k * MF + m0 + mm];
    }
    __syncthreads();
#pragma unroll
    for (int i = 0; i < 8; i++) {
        int f = i * 256 + tid, mm = f >> 5, kq = (f & 31) * 4;
        uint32_t p0 = pack2h(tile[kq * 65 + mm],       tile[(kq + 1) * 65 + mm]);
        uint32_t p1 = pack2h(tile[(kq + 2) * 65 + mm], tile[(kq + 3) * 65 + mm]);
        int kt = kq >> 6, kl = kq & 63;
        size_t base = ((size_t)kt * 4 + mt) * TS;
        uint32_t off = swz((uint32_t)(mm * 128 + kl * 2)) >> 1;
        *(uint2*)&g_omT[base + off] = make_uint2(p0, p1);
    }
}

// ---------------- vT: f16(s*V) swizzled tiles + V colsum partials ----------------
#define VT_SMEM (64 * 129 * 4 + 256)
__global__ __launch_bounds__(256)
void vT_kernel(const float* __restrict__ V) {
    extern __shared__ char smem[];
    float* tile = (float*)smem;                       // [64 n][129 v]
    float* s_sm = (float*)(smem + 64 * 129 * 4);      // [64]
    const int tid = threadIdx.x;
    const int nt = blockIdx.x, n0 = nt * 64, v0 = blockIdx.y * 128;
    if (tid < 64) s_sm[tid] = __expf(g_rowmax[n0 + tid] - o2f(g_segmax[n0 >> 9]));
#pragma unroll
    for (int i = 0; i < 32; i++) {
        int f = i * 256 + tid, n = f >> 7, v = f & 127;
        tile[n * 129 + v] = V[(size_t)(n0 + n) * DV + v0 + v];
    }
    __syncthreads();
#pragma unroll
    for (int i = 0; i < 8; i++) {
        int f = i * 256 + tid, v = f >> 4, nq = (f & 15) * 4;
        uint32_t p0 = pack2h(tile[nq * 129 + v] * s_sm[nq],
                             tile[(nq + 1) * 129 + v] * s_sm[nq + 1]);
        uint32_t p1 = pack2h(tile[(nq + 2) * 129 + v] * s_sm[nq + 2],
                             tile[(nq + 3) * 129 + v] * s_sm[nq + 3]);
        int vt = (v0 >> 6) + (v >> 6), vr = v & 63;
        size_t base = ((size_t)nt * 4 + vt) * TS;
        uint32_t off = swz((uint32_t)(vr * 128 + nq * 2)) >> 1;
        *(uint2*)&g_VT[base + off] = make_uint2(p0, p1);
    }
    if (tid < 128) {
        float s = 0.f;
#pragma unroll 4
        for (int n = 0; n < 64; n++) s += tile[n * 129 + tid];
        g_SVp[(size_t)nt * 256 + v0 + tid] = s;
    }
}

// ---------------- phi (fused Q+K): 64-tok x 256-feat, f16x2 (A hi+lo, omega hi) ----------------
#define PHI_MBAR  1920
#define PHI_A0H   2048
#define PHI_A0L   (PHI_A0H + TSB)
#define PHI_A1H   (PHI_A0L + TSB)
#define PHI_A1L   (PHI_A1H + TSB)
#define PHI_B0    (PHI_A1L + TSB)         /* 34816 */
#define PHI_B1    (PHI_B0 + 4 * TSB)      /* 67584 */
#define PHI_DBUF  34816                   /* u32 [64][129], overlaps B after gemm */
#define PHI_SMEM  100352

__global__ __launch_bounds__(256, 2)
void phi_kernel(const float* __restrict__ Q, const float* __restrict__ K)
{
    extern __shared__ char smem[];
    const uint32_t sb = smem_u32(smem);
    const int tid = threadIdx.x, wid = tid >> 5, lane = tid & 31;
    const bool isq = blockIdx.x < 512;
    const int tile = blockIdx.x & 511;
    const int row0 = tile * 64;
    const float* X = isq ? Q : K;
    const int m0 = (wid & 1) * 32, n0 = (wid >> 1) * 64, warpN = wid >> 1;

    float* h_sm    = (float*)smem;               // [64]
    float* rmax_sm = (float*)(smem + 256);       // [64]
    float* rmaxp   = (float*)(smem + 512);       // [64][4]
    float* wm_sm   = (float*)(smem + 1536);      // [2]
    float* bmax_s  = (float*)(smem + 1568);      // [1]
    float* w_sm    = (float*)(smem + 1600);      // [64]
    uint32_t* dbuf16 = (uint32_t*)(smem + PHI_DBUF);  // [64][129] f16x2

    if (tid == 0) {
        MBAR_INIT(sb + PHI_MBAR, 1);
        MBAR_EXPECT(sb + PHI_MBAR, 65536);
        BULK_G2S(sb + PHI_B0, g_omT, 32768, sb + PHI_MBAR);
        BULK_G2S(sb + PHI_B1, g_omT + (size_t)4 * TS, 32768, sb + PHI_MBAR);
    }

    // A: load X full K=128, scale, h, split hi/lo into 2 k-tiles
    const int arow = tid >> 2, aq = tid & 3;
    float hp = 0.f;
#pragma unroll
    for (int j = 0; j < 8; j++) {
        int k = aq * 32 + j * 4;
        float4 v = *(const float4*)(X + (size_t)(row0 + arow) * DQK + k);
        v.x *= INV_D4; v.y *= INV_D4; v.z *= INV_D4; v.w *= INV_D4;
        hp += v.x * v.x + v.y * v.y + v.z * v.z + v.w * v.w;
        uint16_t h0, l0, h1, l1, h2, l2, h3, l3;
        split1h(v.x, h0, l0); split1h(v.y, h1, l1);
        split1h(v.z, h2, l2); split1h(v.w, h3, l3);
        uint32_t hw0 = (uint32_t)h0 | ((uint32_t)h1 << 16);
        uint32_t hw1 = (uint32_t)h2 | ((uint32_t)h3 << 16);
        uint32_t lw0 = (uint32_t)l0 | ((uint32_t)l1 << 16);
        uint32_t lw1 = (uint32_t)l2 | ((uint32_t)l3 << 16);
        int kt = k >> 6, kl = k & 63;
        uint32_t off = swz((uint32_t)(arow * 128 + kl * 2));
        uint32_t ah = kt ? PHI_A1H : PHI_A0H;
        uint32_t al = kt ? PHI_A1L : PHI_A0L;
        *(uint2*)(smem + ah + off) = make_uint2(hw0, hw1);
        *(uint2*)(smem + al + off) = make_uint2(lw0, lw1);
    }
    hp += __shfl_xor_sync(0xffffffffu, hp, 1);
    hp += __shfl_xor_sync(0xffffffffu, hp, 2);
    if ((lane & 3) == 0) h_sm[arow] = 0.5f * hp;

    float c[2][8][4];
#pragma unroll
    for (int mt = 0; mt < 2; mt++)
#pragma unroll
        for (int nt = 0; nt < 8; nt++)
#pragma unroll
            for (int q = 0; q < 4; q++) c[mt][nt][q] = 0.f;

    MBAR_WAIT(sb + PHI_MBAR, 0);
    __syncthreads();
    gemm_t<true>(c, sb + PHI_A0H, sb + PHI_A0L, sb + PHI_B0, lane, m0, n0);
    gemm_t<true>(c, sb + PHI_A1H, sb + PHI_A1L, sb + PHI_B1, lane, m0, n0);
    __syncthreads();

    float rmx[2][2] = {{-3.0e38f, -3.0e38f}, {-3.0e38f, -3.0e38f}};
#pragma unroll
    for (int mt = 0; mt < 2; mt++)
#pragma unroll
        for (int nt = 0; nt < 8; nt++) {
            rmx[mt][0] = fmaxf(rmx[mt][0], fmaxf(c[mt][nt][0], c[mt][nt][1]));
            rmx[mt][1] = fmaxf(rmx[mt][1], fmaxf(c[mt][nt][2], c[mt][nt][3]));
        }
#pragma unroll
    for (int mt = 0; mt < 2; mt++)
#pragma unroll
        for (int hh = 0; hh < 2; hh++) {
            float v = rmx[mt][hh];
            v = fmaxf(v, __shfl_xor_sync(0xffffffffu, v, 1));
            v = fmaxf(v, __shfl_xor_sync(0xffffffffu, v, 2));
            rmx[mt][hh] = v;
        }
    {
        int g = lane >> 2;
        if ((lane & 3) == 0) {
            rmaxp[(m0 + g) * 4 + warpN]      = rmx[0][0];
            rmaxp[(m0 + g + 8) * 4 + warpN]  = rmx[0][1];
            rmaxp[(m0 + 16 + g) * 4 + warpN] = rmx[1][0];
            rmaxp[(m0 + 24 + g) * 4 + warpN] = rmx[1][1];
        }
    }
    __syncthreads();
    if (tid < 64) {
        float rm = fmaxf(fmaxf(rmaxp[tid * 4], rmaxp[tid * 4 + 1]),
                         fmaxf(rmaxp[tid * 4 + 2], rmaxp[tid * 4 + 3]));
        rmax_sm[tid] = rm;
        if (!isq) {
            g_rowmax[row0 + tid] = rm;
            float bm = warpMax(rm);
            if (lane == 0) wm_sm[wid] = bm;
        }
    }
    __syncthreads();
    if (!isq) {
        if (tid == 0) {
            float bm = fmaxf(wm_sm[0], wm_sm[1]);
            bmax_s[0] = bm;
            g_bmax[tile] = bm;
            atomicMax(&g_segmax[tile >> 3], f2o(bm));
        }
        __syncthreads();
        if (tid < 64) w_sm[tid] = __expf(rmax_sm[tid] - bmax_s[0]);
    }

    if (isq) {
        // Qp = exp2(y) + eps (f16x2 path), direct tile stores
        const __half2 eps2 = __float2half2_rn(EPS_PHI);
        int g = lane >> 2, j = lane & 3;
#pragma unroll
        for (int mt = 0; mt < 2; mt++) {
            int r0 = m0 + mt * 16 + g, r1 = r0 + 8;
            float hm0 = (h_sm[r0] + rmax_sm[r0]) * LOG2E;
            float hm1 = (h_sm[r1] + rmax_sm[r1]) * LOG2E;
#pragma unroll
            for (int nt = 0; nt < 8; nt++) {
                int col = n0 + nt * 8 + j * 2;
                uint32_t e01 = exp2_h2(c[mt][nt][0] * LOG2E - hm0,
                                       c[mt][nt][1] * LOG2E - hm0);
                uint32_t e23 = exp2_h2(c[mt][nt][2] * LOG2E - hm1,
                                       c[mt][nt][3] * LOG2E - hm1);
                __half2 q01 = __hadd2(*(__half2*)&e01, eps2);
                __half2 q23 = __hadd2(*(__half2*)&e23, eps2);
                int kt = col >> 6, cl = col & 63;
                size_t base = ((size_t)tile * 4 + kt) * TS;
                uint32_t o0 = swz((uint32_t)(r0 * 128 + cl * 2)) >> 1;
                uint32_t o1 = swz((uint32_t)(r1 * 128 + cl * 2)) >> 1;
                *(uint32_t*)&g_Qp[base + o0] = *(uint32_t*)&q01;
                *(uint32_t*)&g_Qp[base + o1] = *(uint32_t*)&q23;
            }
        }
    } else {
        // Kp0 = exp2(y) -> f16x2 dbuf, transposed tile stores + W partial
        int g = lane >> 2, j = lane & 3;
#pragma unroll
        for (int mt = 0; mt < 2; mt++) {
            int r0 = m0 + mt * 16 + g, r1 = r0 + 8;
            float hm0 = (h_sm[r0] + rmax_sm[r0]) * LOG2E;
            float hm1 = (h_sm[r1] + rmax_sm[r1]) * LOG2E;
#pragma unroll
            for (int nt = 0; nt < 8; nt++) {
                int cc = n0 + nt * 8 + j * 2;
                dbuf16[r0 * 129 + (cc >> 1)] =
                    exp2_h2(c[mt][nt][0] * LOG2E - hm0, c[mt][nt][1] * LOG2E - hm0);
                dbuf16[r1 * 129 + (cc >> 1)] =
                    exp2_h2(c[mt][nt][2] * LOG2E - hm1, c[mt][nt][3] * LOG2E - hm1);
            }
        }
        __syncthreads();
        // KpT tiles: [tok-pairs packed], via PRMT half selects
#pragma unroll 4
        for (int i = 0; i < 32; i++) {
            int f = i * 256 + tid, feat = f >> 5, tp = (f & 31) * 2;
            uint32_t a = dbuf16[tp * 129 + (feat >> 1)];
            uint32_t b = dbuf16[(tp + 1) * 129 + (feat >> 1)];
            uint32_t res = (feat & 1) ? prmt(a, b, 0x7632u) : prmt(a, b, 0x5410u);
            int ft = feat >> 6, fl = feat & 63;
            size_t base = ((size_t)tile * 4 + ft) * TS;
            uint32_t off = swz((uint32_t)(fl * 128 + tp * 2)) >> 1;
            *(uint32_t*)&g_KpT[base + off] = res;
        }
        // W[feat] = sum_tok e * w
        float s = 0.f;
        const uint32_t* drow = dbuf16 + (tid >> 1);
#pragma unroll 4
        for (int t = 0; t < 64; t++) {
            uint32_t p = drow[t * 129];
            __half2 h2 = *(__half2*)&p;
            float e = (tid & 1) ? __high2float(h2) : __low2float(h2);
            s += e * w_sm[t];
        }
        g_W[tile * 256 + tid] = s;
    }
}

// ---------------- kv: tile 128m x 128v, 256 thr, 2 CTA/SM, depth-3 bulk pipeline ----------------
#define KV_ST0  2048
#define KV_ST1  34816
#define KV_ST2  67584
#define KV_SV   100352
#define KV_SMEM 100864

__global__ __launch_bounds__(256, 2)
void kv_kernel()
{
    extern __shared__ char smem[];
    const uint32_t sb = smem_u32(smem);
    const int tid = threadIdx.x, wid = tid >> 5, lane = tid & 31;
    const int b = blockIdx.x >> 2, mt_ = (blockIdx.x >> 1) & 1, vh = blockIdx.x & 1;
    const int v0 = vh * 128;
    const int m0 = (wid & 3) * 32, n0 = (wid >> 2) * 64;
    const uint32_t stg[3] = { sb + KV_ST0, sb + KV_ST1, sb + KV_ST2 };

    if (tid == 0) { MBAR_INIT(sb + 0, 1); MBAR_INIT(sb + 8, 1); MBAR_INIT(sb + 16, 1); }
    float* sv = (float*)(smem + KV_SV);            // [128]
    if (tid < 128) {
        const float* P = g_SVp + (size_t)(8 * b) * 256 + v0 + tid;
        float s = 0.f;
#pragma unroll
        for (int t = 0; t < 8; t++) s += P[t * 256];
        sv[tid] = s * EPS_PHI;
    }
    __syncthreads();

    float c[2][8][4];
#pragma unroll
    for (int mt = 0; mt < 2; mt++)
#pragma unroll
        for (int nt = 0; nt < 8; nt++)
#pragma unroll
            for (int q = 0; q < 4; q++) c[mt][nt][q] = 0.f;

    if (tid == 0) {
#pragma unroll
        for (int pf = 0; pf < 2; pf++) {
            size_t tt = (size_t)(b * 8 + pf) * 4;
            uint32_t mb = sb + pf * 8;
            MBAR_EXPECT(mb, 32768);
            BULK_G2S(stg[pf],         g_KpT + (tt + mt_ * 2) * TS, 16384, mb);
            BULK_G2S(stg[pf] + 16384, g_VT  + (tt + vh * 2) * TS, 16384, mb);
        }
    }
    for (int ch = 0; ch < 8; ch++) {
        if (ch < 6 && tid == 0) {
            int nf = ch + 2, bi = nf % 3;
            uint32_t mb = sb + bi * 8;
            size_t tt = (size_t)(b * 8 + nf) * 4;
            MBAR_EXPECT(mb, 32768);
            BULK_G2S(stg[bi],         g_KpT + (tt + mt_ * 2) * TS, 16384, mb);
            BULK_G2S(stg[bi] + 16384, g_VT  + (tt + vh * 2) * TS, 16384, mb);
        }
        int bi = ch % 3;
        MBAR_WAIT(sb + bi * 8, (ch / 3) & 1);
        gemm_t<false>(c, stg[bi], 0, stg[bi] + 16384, lane, m0, n0);
        __syncthreads();
    }

    // epilogue: KVT tiles = f16(D + eps*SV)
    float* dbuf = (float*)(smem + 2048);           // [128][129] f32, overlaps stages
    frag_to_dbuf<129>(dbuf, c, lane, m0, n0);
    __syncthreads();
#pragma unroll
    for (int i = 0; i < 16; i++) {
        int f = i * 256 + tid, v = f >> 5, q = (f & 31) * 4;
        float base = sv[v];
        uint32_t p0 = pack2h(dbuf[q * 129 + v] + base, dbuf[(q + 1) * 129 + v] + base);
        uint32_t p1 = pack2h(dbuf[(q + 2) * 129 + v] + base, dbuf[(q + 3) * 129 + v] + base);
        int kt = mt_ * 2 + (q >> 6), vt = vh * 2 + (v >> 6);
        size_t tbase = ((size_t)b * 16 + kt * 4 + vt) * TS;
        uint32_t off = swz((uint32_t)((v & 63) * 128 + (q & 63) * 2)) >> 1;
        *(uint2*)&g_KVT[tbase + off] = make_uint2(p0, p1);
    }
}

// ---------------- out: tile 128row x 128v, 256 thr, 2 CTA/SM, depth-3 bulk, norm fused ----------------
#define OU_ST0  2048
#define OU_ST1  34816
#define OU_ST2  67584
#define OU_KSUM 100352
#define OU_WT   101376
#define OU_NRM  101440
#define OU_SMEM 101952

__global__ __launch_bounds__(256, 2)
void out_kernel(float* __restrict__ Out)
{
    extern __shared__ char smem[];
    const uint32_t sb = smem_u32(smem);
    const int tid = threadIdx.x, wid = tid >> 5, lane = tid & 31;
    const int b = blockIdx.x >> 3, rt = (blockIdx.x >> 1) & 3, vh = blockIdx.x & 1;
    const int row0 = b * NPER + rt * 128;
    const int rt0 = row0 >> 6;
    const int m0 = (wid & 3) * 32, n0 = (wid >> 2) * 64;
    float* ksum   = (float*)(smem + OU_KSUM);      // [256]
    float* wtp    = (float*)(smem + OU_WT);        // [8]
    float* nrm_sm = (float*)(smem + OU_NRM);       // [128]
    const uint32_t stg[3] = { sb + OU_ST0, sb + OU_ST1, sb + OU_ST2 };

    if (tid == 0) { MBAR_INIT(sb + 0, 1); MBAR_INIT(sb + 8, 1); MBAR_INIT(sb + 16, 1); }
    if (tid < 8) wtp[tid] = __expf(g_bmax[b * 8 + tid] - o2f(g_segmax[b]));
    __syncthreads();
    {
        float s = 0.f;
#pragma unroll
        for (int t = 0; t < 8; t++) s += g_W[(size_t)(8 * b + t) * 256 + tid] * wtp[t];
        ksum[tid] = s + 512.0f * EPS_PHI;
    }
    __syncthreads();

    float c[2][8][4];
#pragma unroll
    for (int mt = 0; mt < 2; mt++)
#pragma unroll
        for (int nt = 0; nt < 8; nt++)
#pragma unroll
            for (int q = 0; q < 4; q++) c[mt][nt][q] = 0.f;

    const int qrow = tid >> 1, qoff = (tid & 1) * 32;
    float qd = 0.f;

    if (tid == 0) {
#pragma unroll
        for (int pf = 0; pf < 2; pf++) {
            uint32_t mb = sb + pf * 8;
            MBAR_EXPECT(mb, 32768);
            BULK_G2S(stg[pf],        g_Qp + ((size_t)rt0 * 4 + pf) * TS, 8192, mb);
            BULK_G2S(stg[pf] + TSB,  g_Qp + ((size_t)(rt0 + 1) * 4 + pf) * TS, 8192, mb);
            BULK_G2S(stg[pf] + 16384, g_KVT + ((size_t)b * 16 + pf * 4 + vh * 2) * TS, 16384, mb);
        }
    }
    for (int ch = 0; ch < 4; ch++) {
        if (ch < 2 && tid == 0) {
            int nf = ch + 2, bi = nf % 3;
            uint32_t mb = sb + bi * 8;
            MBAR_EXPECT(mb, 32768);
            BULK_G2S(stg[bi],        g_Qp + ((size_t)rt0 * 4 + nf) * TS, 8192, mb);
            BULK_G2S(stg[bi] + TSB,  g_Qp + ((size_t)(rt0 + 1) * 4 + nf) * TS, 8192, mb);
            BULK_G2S(stg[bi] + 16384, g_KVT + ((size_t)b * 16 + nf * 4 + vh * 2) * TS, 16384, mb);
        }
        int bi = ch % 3;
        MBAR_WAIT(sb + bi * 8, (ch / 3) & 1);
        // qdot partial from staged Qp against ksum
        {
            const char* AH = (const char*)smem + (stg[bi] - sb);
            uint32_t tb = (uint32_t)(qrow >> 6) * TSB + (uint32_t)(qrow & 63) * 128u;
            uint32_t rx = (uint32_t)(qrow & 7) << 4;
            int k0 = ch * 64;
            float qp = 0.f;
#pragma unroll
            for (int jq = 0; jq < 8; jq++) {
                uint32_t o = tb + (((uint32_t)(qoff + jq * 4) * 2) ^ rx);
                uint2 h2 = *(const uint2*)(AH + o);
                const uint16_t* hp = (const uint16_t*)&h2;
#pragma unroll
                for (int j = 0; j < 4; j++)
                    qp += h2f(hp[j]) * ksum[k0 + qoff + jq * 4 + j];
            }
            qd += qp;
        }
        gemm_t<false>(c, stg[bi], 0, stg[bi] + 16384, lane, m0, n0);
        __syncthreads();
    }

    qd += __shfl_xor_sync(0xffffffffu, qd, 1);
    if ((tid & 1) == 0) nrm_sm[qrow] = 1.0f / (qd + EPS_NORM_S);
    __syncthreads();

    // direct fragment stores / norm
    {
        int g = lane >> 2, j = lane & 3;
#pragma unroll
        for (int mt = 0; mt < 2; mt++) {
            int r0 = m0 + mt * 16 + g, r1 = r0 + 8;
            float inv0 = nrm_sm[r0], inv1 = nrm_sm[r1];
#pragma unroll
            for (int nt = 0; nt < 8; nt++) {
                int cc = vh * 128 + n0 + nt * 8 + j * 2;
                float2 o0 = make_float2(c[mt][nt][0] * inv0, c[mt][nt][1] * inv0);
                float2 o1 = make_float2(c[mt][nt][2] * inv1, c[mt][nt][3] * inv1);
                *(float2*)(Out + (size_t)(row0 + r0) * DV + cc) = o0;
                *(float2*)(Out + (size_t)(row0 + r1) * DV + cc) = o1;
            }
        }
    }
}

// ---------------- launch ----------------
extern "C" void kernel_launch(void* const* d_in, const int* in_sizes, int n_in,
                              void* d_out, int out_size)
{
    (void)in_sizes; (void)n_in; (void)out_size;
    const float* Q     = (const float*)d_in[0];
    const float* K     = (const float*)d_in[1];
    const float* V     = (const float*)d_in[2];
    const float* omega = (const float*)d_in[3];
    float* Out = (float*)d_out;

    cudaFuncSetAttribute(omT_kernel,  cudaFuncAttributeMaxDynamicSharedMemorySize, OMT_SMEM);
    cudaFuncSetAttribute(vT_kernel,   cudaFuncAttributeMaxDynamicSharedMemorySize, VT_SMEM);
    cudaFuncSetAttribute(phi_kernel,  cudaFuncAttributeMaxDynamicSharedMemorySize, PHI_SMEM);
    cudaFuncSetAttribute(kv_kernel,   cudaFuncAttributeMaxDynamicSharedMemorySize, KV_SMEM);
    cudaFuncSetAttribute(out_kernel,  cudaFuncAttributeMaxDynamicSharedMemorySize, OU_SMEM);

    omT_kernel<<<4, 256, OMT_SMEM>>>(omega);
    phi_kernel<<<1024, 256, PHI_SMEM>>>(Q, K);
    vT_kernel<<<dim3(512, 2), 256, VT_SMEM>>>(V);
    kv_kernel<<<256, 256, KV_SMEM>>>();
    out_kernel<<<512, 256, OU_SMEM>>>(Out);
}